// round 12
// baseline (speedup 1.0000x reference)
#include <cuda_runtime.h>
#include <cuda_bf16.h>
#include <stdint.h>

// ---------------- problem constants ----------------
constexpr int Sdim = 2048, Hdim = 16, BHdim = 64, Ddim = 64;
constexpr int TQ = 64;            // query rows per CTA
constexpr int NK = 64;            // key slab
constexpr int NSLAB = Sdim / NK;  // 32

constexpr int TSTR = 144;         // bytes per bf16 tile row
constexpr int TILE_B = NK * TSTR;            // 9216
constexpr int SLAB_B = 4 * TILE_B;           // KS_HI|KS_LO|VS_HI|VS_LO
__device__ __align__(16) unsigned char g_kv[(size_t)BHdim * NSLAB * SLAB_B];

// ---------------- smem layout (byte offsets) ----------------
constexpr int RS_B    = 0;
constexpr int INV_B   = 256;
constexpr int PM_B    = 512;      // int[2][64]
constexpr int QS_HI_B = 1024;
constexpr int QS_LO_B = 10240;
constexpr int KV0_B   = 19456;    // 2 x 36864
constexpr int PS_HI_B = 93184;
constexpr int PS_LO_B = 102400;
constexpr int SMEM_TOTAL = 111616;   // 109 KB -> 2 CTAs/SM

// ---------------- helpers ----------------
__device__ __forceinline__ uint32_t smem_u32(const void* p) {
    uint32_t a;
    asm("{ .reg .u64 t; cvta.to.shared.u64 t, %1; cvt.u32.u64 %0, t; }" : "=r"(a) : "l"(p));
    return a;
}
__device__ __forceinline__ void cp16(uint32_t sdst, const void* gsrc) {
    asm volatile("cp.async.cg.shared.global [%0], [%1], 16;" :: "r"(sdst), "l"(gsrc));
}
__device__ __forceinline__ void ldsm4(uint32_t addr, uint32_t& r0, uint32_t& r1,
                                      uint32_t& r2, uint32_t& r3) {
    asm volatile("ldmatrix.sync.aligned.m8n8.x4.shared.b16 {%0,%1,%2,%3}, [%4];"
                 : "=r"(r0), "=r"(r1), "=r"(r2), "=r"(r3) : "r"(addr));
}
__device__ __forceinline__ void ldsm4t(uint32_t addr, uint32_t& r0, uint32_t& r1,
                                       uint32_t& r2, uint32_t& r3) {
    asm volatile("ldmatrix.sync.aligned.m8n8.x4.trans.shared.b16 {%0,%1,%2,%3}, [%4];"
                 : "=r"(r0), "=r"(r1), "=r"(r2), "=r"(r3) : "r"(addr));
}
__device__ __forceinline__ void mma16816(float* c, uint32_t a0, uint32_t a1,
                                         uint32_t a2, uint32_t a3,
                                         uint32_t b0, uint32_t b1) {
    asm volatile(
        "mma.sync.aligned.m16n8k16.row.col.f32.bf16.bf16.f32 "
        "{%0,%1,%2,%3}, {%4,%5,%6,%7}, {%8,%9}, {%0,%1,%2,%3};"
        : "+f"(c[0]), "+f"(c[1]), "+f"(c[2]), "+f"(c[3])
        : "r"(a0), "r"(a1), "r"(a2), "r"(a3), "r"(b0), "r"(b1));
}
__device__ __forceinline__ void split2(char* hiB, char* loB, int off, float a, float b) {
    __nv_bfloat16 ah = __float2bfloat16_rn(a);
    __nv_bfloat16 bh = __float2bfloat16_rn(b);
    __nv_bfloat16 al = __float2bfloat16_rn(a - __bfloat162float(ah));
    __nv_bfloat16 bl = __float2bfloat16_rn(b - __bfloat162float(bh));
    *(__nv_bfloat162*)(hiB + off) = __halves2bfloat162(ah, bh);
    *(__nv_bfloat162*)(loB + off) = __halves2bfloat162(al, bl);
}

// ================= preprocessing: K,V fp32 -> tiled bf16 hi/lo =================
__global__ __launch_bounds__(256)
void prep_kv(const float* __restrict__ K, const float* __restrict__ V)
{
    const int s  = blockIdx.x;
    const int bh = blockIdx.y;
    const int tid = threadIdx.x;
    const float* Kb = K + ((size_t)bh * Sdim + s * NK) * Ddim;
    const float* Vb = V + ((size_t)bh * Sdim + s * NK) * Ddim;
    char* dst = (char*)g_kv + ((size_t)bh * NSLAB + s) * SLAB_B;

    for (int i = tid; i < NK * Ddim / 4; i += 256) {
        int k = i >> 4, db = (i & 15) * 4;
        int off = k * TSTR + db * 2;
        float4 kv4 = *(const float4*)(Kb + (size_t)k * Ddim + db);
        split2(dst,              dst + TILE_B,     off,     kv4.x, kv4.y);
        split2(dst,              dst + TILE_B,     off + 4, kv4.z, kv4.w);
        float4 vv4 = *(const float4*)(Vb + (size_t)k * Ddim + db);
        split2(dst + 2 * TILE_B, dst + 3 * TILE_B, off,     vv4.x, vv4.y);
        split2(dst + 2 * TILE_B, dst + 3 * TILE_B, off + 4, vv4.z, vv4.w);
    }
}

// ================= fused attention (round-8 structure + ldsm dedup + .cs) ============
__global__ __launch_bounds__(256, 2)
void attn_fused(const float* __restrict__ Q, const int* __restrict__ pad,
                float* __restrict__ outO, float* __restrict__ outW)
{
    extern __shared__ __align__(16) char sm[];
    const int tid  = threadIdx.x;
    const int wid  = tid >> 5;
    const int lane = tid & 31;
    const int bh   = blockIdx.y;
    const int q0   = blockIdx.x * TQ;
    const int b    = bh / Hdim;

    const uint32_t smb = smem_u32(sm);
    float* rowsum = (float*)(sm + RS_B);
    float* invp   = (float*)(sm + INV_B);
    int*   pmp    = (int*)(sm + PM_B);

    const float* Qb = Q + ((size_t)bh * Sdim + q0) * Ddim;
    const int*   pb = pad + (size_t)b * Sdim;
    const char*  Gkv = (const char*)g_kv + (size_t)bh * NSLAB * SLAB_B;
    float* Wb = outW + ((size_t)bh * Sdim + q0) * Sdim;

    // ---- prologue ----
    for (int i = tid; i < TQ * Ddim / 4; i += 256) {
        int q = i >> 4, db = (i & 15) * 4;
        float4 v = *(const float4*)(Qb + (size_t)q * Ddim + db);
        int base = q * TSTR + db * 2;
        split2(sm + QS_HI_B, sm + QS_LO_B, base,     v.x, v.y);
        split2(sm + QS_HI_B, sm + QS_LO_B, base + 4, v.z, v.w);
    }
    #pragma unroll
    for (int i = 0; i < SLAB_B / 16 / 256; ++i)
        cp16(smb + KV0_B + (tid + i * 256) * 16, Gkv + (tid + i * 256) * 16);
    asm volatile("cp.async.commit_group;" ::: "memory");
    if (tid < NK) pmp[tid] = pb[tid];
    if (tid < TQ) rowsum[tid] = 0.f;
    __syncthreads();

    const int wq = wid & 3;
    const int wk = wid >> 2;
    const int arow  = lane & 15;
    const int apart = (lane >> 4) * 16;
    const int brow  = (lane & 7) + ((lane >> 4) << 3);
    const int bpart = ((lane >> 3) & 1) * 16;
    const int vrow  = (lane & 7) + (((lane >> 3) & 1) << 3);
    const int vpart = (lane >> 4) * 16;
    const int rlo = wq * 16 + (lane >> 2);
    float rs_lo = 0.f, rs_hi = 0.f;

    // hoist Q A-fragments
    uint32_t aH[4][4], aL[4][4];
    #pragma unroll
    for (int ks = 0; ks < 4; ++ks) {
        ldsm4(smb + QS_HI_B + (wq * 16 + arow) * TSTR + ks * 32 + apart,
              aH[ks][0], aH[ks][1], aH[ks][2], aH[ks][3]);
        ldsm4(smb + QS_LO_B + (wq * 16 + arow) * TSTR + ks * 32 + apart,
              aL[ks][0], aL[ks][1], aL[ks][2], aL[ks][3]);
    }

    float co[4][4];
    #pragma unroll
    for (int n = 0; n < 4; ++n)
        #pragma unroll
        for (int j = 0; j < 4; ++j) co[n][j] = 0.f;

    const int qglo = q0 + rlo, qghi = qglo + 8;

    // ======================= mainloop =======================
    for (int s = 0; s < NSLAB; ++s) {
        const int buf = s & 1;
        const uint32_t KV = smb + KV0_B + buf * SLAB_B;

        asm volatile("cp.async.wait_group 0;" ::: "memory");
        __syncthreads();   // slab s visible; PV readers of buf^1 done

        // kick next slab copy + pad mask
        if (s + 1 < NSLAB) {
            const char* gsrc = Gkv + (size_t)(s + 1) * SLAB_B;
            const uint32_t sdst = smb + KV0_B + (buf ^ 1) * SLAB_B;
            #pragma unroll
            for (int i = 0; i < SLAB_B / 16 / 256; ++i)
                cp16(sdst + (tid + i * 256) * 16, gsrc + (tid + i * 256) * 16);
            asm volatile("cp.async.commit_group;" ::: "memory");
            if (tid < NK) pmp[(buf ^ 1) * 64 + tid] = pb[(s + 1) * NK + tid];
        }

        // ---- QK^T(s): ks-major, each unique B fragment loaded once ----
        float c[4][4];
        #pragma unroll
        for (int n = 0; n < 4; ++n)
            #pragma unroll
            for (int j = 0; j < 4; ++j) c[n][j] = 0.f;

        #pragma unroll
        for (int ks = 0; ks < 4; ++ks) {
            #pragma unroll
            for (int nt2 = 0; nt2 < 2; ++nt2) {
                const uint32_t boff = (wk * 32 + nt2 * 16 + brow) * TSTR + ks * 32 + bpart;
                uint32_t h0, h1, h2, h3, l0, l1, l2, l3;
                ldsm4(KV + boff,          h0, h1, h2, h3);   // K_hi
                ldsm4(KV + TILE_B + boff, l0, l1, l2, l3);   // K_lo
                // hiQ*hiK + hiQ*loK + loQ*hiK
                mma16816(c[2 * nt2],     aH[ks][0], aH[ks][1], aH[ks][2], aH[ks][3], h0, h1);
                mma16816(c[2 * nt2 + 1], aH[ks][0], aH[ks][1], aH[ks][2], aH[ks][3], h2, h3);
                mma16816(c[2 * nt2],     aH[ks][0], aH[ks][1], aH[ks][2], aH[ks][3], l0, l1);
                mma16816(c[2 * nt2 + 1], aH[ks][0], aH[ks][1], aH[ks][2], aH[ks][3], l2, l3);
                mma16816(c[2 * nt2],     aL[ks][0], aL[ks][1], aL[ks][2], aL[ks][3], h0, h1);
                mma16816(c[2 * nt2 + 1], aL[ks][0], aL[ks][1], aL[ks][2], aL[ks][3], h2, h3);
            }
        }

        // ---- epilogue(s): mask/exp, rowsum, W store (unnorm, streaming), split -> PS ----
        const int* pmb = pmp + buf * 64;
        const int k0 = s * NK;
        #pragma unroll
        for (int nt = 0; nt < 4; ++nt) {
            const int col = wk * 32 + nt * 8 + (lane & 3) * 2;
            const int kg  = k0 + col;
            const int p0 = pmb[col], p1 = pmb[col + 1];
            float e0 = (((kg     > qglo) + p0) == 1) ? 0.f : __expf(c[nt][0] * 0.125f);
            float e1 = (((kg + 1 > qglo) + p1) == 1) ? 0.f : __expf(c[nt][1] * 0.125f);
            float e2 = (((kg     > qghi) + p0) == 1) ? 0.f : __expf(c[nt][2] * 0.125f);
            float e3 = (((kg + 1 > qghi) + p1) == 1) ? 0.f : __expf(c[nt][3] * 0.125f);
            rs_lo += e0 + e1;
            rs_hi += e2 + e3;
            __stcs((float2*)&Wb[(size_t)rlo * Sdim + kg],       make_float2(e0, e1));
            __stcs((float2*)&Wb[(size_t)(rlo + 8) * Sdim + kg], make_float2(e2, e3));
            split2(sm + PS_HI_B, sm + PS_LO_B, rlo * TSTR + col * 2,       e0, e1);
            split2(sm + PS_HI_B, sm + PS_LO_B, (rlo + 8) * TSTR + col * 2, e2, e3);
        }
        __syncthreads();   // PS columns span both wk warps

        // ---- PV(s): ks-major, A and B fragments each loaded once ----
        #pragma unroll
        for (int ks = 0; ks < 4; ++ks) {
            const uint32_t aoff = (wq * 16 + arow) * TSTR + ks * 32 + apart;
            uint32_t pH[4], pL[4];
            ldsm4(smb + PS_HI_B + aoff, pH[0], pH[1], pH[2], pH[3]);
            ldsm4(smb + PS_LO_B + aoff, pL[0], pL[1], pL[2], pL[3]);
            #pragma unroll
            for (int nt2 = 0; nt2 < 2; ++nt2) {
                const uint32_t voff = (ks * 16 + vrow) * TSTR + (wk * 32 + nt2 * 16) * 2 + vpart;
                uint32_t h0, h1, h2, h3, l0, l1, l2, l3;
                ldsm4t(KV + 2 * TILE_B + voff, h0, h1, h2, h3);   // V_hi
                ldsm4t(KV + 3 * TILE_B + voff, l0, l1, l2, l3);   // V_lo
                // hiP*hiV + hiP*loV + loP*hiV
                mma16816(co[2 * nt2],     pH[0], pH[1], pH[2], pH[3], h0, h1);
                mma16816(co[2 * nt2 + 1], pH[0], pH[1], pH[2], pH[3], h2, h3);
                mma16816(co[2 * nt2],     pH[0], pH[1], pH[2], pH[3], l0, l1);
                mma16816(co[2 * nt2 + 1], pH[0], pH[1], pH[2], pH[3], l2, l3);
                mma16816(co[2 * nt2],     pL[0], pL[1], pL[2], pL[3], h0, h1);
                mma16816(co[2 * nt2 + 1], pL[0], pL[1], pL[2], pL[3], h2, h3);
            }
        }
    }

    // ---- rowsums -> inv ----
    rs_lo += __shfl_xor_sync(0xffffffffu, rs_lo, 1);
    rs_lo += __shfl_xor_sync(0xffffffffu, rs_lo, 2);
    rs_hi += __shfl_xor_sync(0xffffffffu, rs_hi, 1);
    rs_hi += __shfl_xor_sync(0xffffffffu, rs_hi, 2);
    if ((lane & 3) == 0) {
        atomicAdd(&rowsum[rlo], rs_lo);
        atomicAdd(&rowsum[rlo + 8], rs_hi);
    }
    __syncthreads();
    if (tid < TQ) invp[tid] = 1.0f / rowsum[tid];
    __syncthreads();

    // ---- O store (normalize accumulators) ----
    {
        const float ivlo = invp[rlo], ivhi = invp[rlo + 8];
        #pragma unroll
        for (int nt = 0; nt < 4; ++nt) {
            const int col = wk * 32 + nt * 8 + (lane & 3) * 2;
            const size_t r0o = ((size_t)bh * Sdim + q0 + rlo) * Ddim + col;
            const size_t r1o = ((size_t)bh * Sdim + q0 + rlo + 8) * Ddim + col;
            *(float2*)&outO[r0o] = make_float2(co[nt][0] * ivlo, co[nt][1] * ivlo);
            *(float2*)&outO[r1o] = make_float2(co[nt][2] * ivhi, co[nt][3] * ivhi);
        }
    }

    // ---- W normalize sweep (streaming loads/stores) ----
    for (int i = tid; i < TQ * (Sdim / 4); i += 256) {
        int q = i >> 9, c4 = (i & 511) * 4;
        float* gw = Wb + (size_t)q * Sdim + c4;
        float4 e = __ldcs((const float4*)gw);
        const float iv = invp[q];
        e.x *= iv; e.y *= iv; e.z *= iv; e.w *= iv;
        __stcs((float4*)gw, e);
    }
}

extern "C" void kernel_launch(void* const* d_in, const int* in_sizes, int n_in,
                              void* d_out, int out_size)
{
    const float* Q   = (const float*)d_in[0];
    const float* K   = (const float*)d_in[1];
    const float* V   = (const float*)d_in[2];
    const int*   pad = (const int*)d_in[3];

    const long long nres = (long long)BHdim * Sdim * Ddim;
    float* outO = (float*)d_out;
    float* outW = outO + nres;   // out = (result, attention_weights)

    dim3 pgrid(NSLAB, BHdim);
    prep_kv<<<pgrid, 256>>>(K, V);

    cudaFuncSetAttribute(attn_fused, cudaFuncAttributeMaxDynamicSharedMemorySize, SMEM_TOTAL);
    dim3 grid(Sdim / TQ, BHdim);
    attn_fused<<<grid, 256, SMEM_TOTAL>>>(Q, pad, outO, outW);
}

// round 13
// speedup vs baseline: 1.1224x; 1.1224x over previous
#include <cuda_runtime.h>
#include <cuda_fp16.h>
#include <stdint.h>

// ---------------- problem constants ----------------
constexpr int Sdim = 2048, Hdim = 16, BHdim = 64, Ddim = 64;
constexpr int TQ = 64;            // query rows per CTA
constexpr int NK = 64;            // key slab
constexpr int NSLAB = Sdim / NK;  // 32

constexpr int TSTR = 144;         // bytes per fp16 tile row (64+8 elems)
constexpr int TILE_B = NK * TSTR;            // 9216
constexpr int SLAB_B = 2 * TILE_B;           // K_HI | V_HI  (fp16, hi parts only)
__device__ __align__(16) unsigned char g_kv[(size_t)BHdim * NSLAB * SLAB_B];

// ---------------- smem layout (byte offsets) ----------------
constexpr int RS_B    = 0;        // f32[64]
constexpr int INV_B   = 256;      // f32[64]
constexpr int PM_B    = 512;      // int[2][64]
constexpr int QS_HI_B = 1024;     // [64][72] fp16 = 9216 each
constexpr int QS_LO_B = 10240;
constexpr int KV0_B   = 19456;    // double-buffered slab: 2 x 18432
constexpr int PS_HI_B = 56320;    // [64][72] fp16
constexpr int PS_LO_B = 65536;
constexpr int SMEM_TOTAL = 74752; // 73 KB -> 2 CTAs/SM

// ---------------- helpers ----------------
__device__ __forceinline__ uint32_t smem_u32(const void* p) {
    uint32_t a;
    asm("{ .reg .u64 t; cvta.to.shared.u64 t, %1; cvt.u32.u64 %0, t; }" : "=r"(a) : "l"(p));
    return a;
}
__device__ __forceinline__ void cp16(uint32_t sdst, const void* gsrc) {
    asm volatile("cp.async.cg.shared.global [%0], [%1], 16;" :: "r"(sdst), "l"(gsrc));
}
__device__ __forceinline__ void ldsm4(uint32_t addr, uint32_t& r0, uint32_t& r1,
                                      uint32_t& r2, uint32_t& r3) {
    asm volatile("ldmatrix.sync.aligned.m8n8.x4.shared.b16 {%0,%1,%2,%3}, [%4];"
                 : "=r"(r0), "=r"(r1), "=r"(r2), "=r"(r3) : "r"(addr));
}
__device__ __forceinline__ void ldsm4t(uint32_t addr, uint32_t& r0, uint32_t& r1,
                                       uint32_t& r2, uint32_t& r3) {
    asm volatile("ldmatrix.sync.aligned.m8n8.x4.trans.shared.b16 {%0,%1,%2,%3}, [%4];"
                 : "=r"(r0), "=r"(r1), "=r"(r2), "=r"(r3) : "r"(addr));
}
__device__ __forceinline__ void mma16816(float* c, uint32_t a0, uint32_t a1,
                                         uint32_t a2, uint32_t a3,
                                         uint32_t b0, uint32_t b1) {
    asm volatile(
        "mma.sync.aligned.m16n8k16.row.col.f32.f16.f16.f32 "
        "{%0,%1,%2,%3}, {%4,%5,%6,%7}, {%8,%9}, {%0,%1,%2,%3};"
        : "+f"(c[0]), "+f"(c[1]), "+f"(c[2]), "+f"(c[3])
        : "r"(a0), "r"(a1), "r"(a2), "r"(a3), "r"(b0), "r"(b1));
}
// fp32 pair -> fp16 hi/lo pairs
__device__ __forceinline__ void split2h(char* hiB, char* loB, int off, float a, float b) {
    __half ah = __float2half_rn(a);
    __half bh = __float2half_rn(b);
    __half al = __float2half_rn(a - __half2float(ah));
    __half bl = __float2half_rn(b - __half2float(bh));
    *(__half2*)(hiB + off) = __halves2half2(ah, bh);
    *(__half2*)(loB + off) = __halves2half2(al, bl);
}
__device__ __forceinline__ void cvt2h(char* dst, int off, float a, float b) {
    *(__half2*)(dst + off) = __halves2half2(__float2half_rn(a), __float2half_rn(b));
}

// ================= preprocessing: K,V fp32 -> tiled fp16 (hi only) =================
__global__ __launch_bounds__(256)
void prep_kv(const float* __restrict__ K, const float* __restrict__ V)
{
    const int s  = blockIdx.x;
    const int bh = blockIdx.y;
    const int tid = threadIdx.x;
    const float* Kb = K + ((size_t)bh * Sdim + s * NK) * Ddim;
    const float* Vb = V + ((size_t)bh * Sdim + s * NK) * Ddim;
    char* dst = (char*)g_kv + ((size_t)bh * NSLAB + s) * SLAB_B;

    for (int i = tid; i < NK * Ddim / 4; i += 256) {
        int k = i >> 4, db = (i & 15) * 4;
        int off = k * TSTR + db * 2;
        float4 kv4 = *(const float4*)(Kb + (size_t)k * Ddim + db);
        cvt2h(dst, off,     kv4.x, kv4.y);
        cvt2h(dst, off + 4, kv4.z, kv4.w);
        float4 vv4 = *(const float4*)(Vb + (size_t)k * Ddim + db);
        cvt2h(dst + TILE_B, off,     vv4.x, vv4.y);
        cvt2h(dst + TILE_B, off + 4, vv4.z, vv4.w);
    }
}

// ================= fused attention: fp16 2-pass =================
__global__ __launch_bounds__(256, 2)
void attn_fused(const float* __restrict__ Q, const int* __restrict__ pad,
                float* __restrict__ outO, float* __restrict__ outW)
{
    extern __shared__ __align__(16) char sm[];
    const int tid  = threadIdx.x;
    const int wid  = tid >> 5;
    const int lane = tid & 31;
    const int bh   = blockIdx.y;
    const int q0   = blockIdx.x * TQ;
    const int b    = bh / Hdim;

    const uint32_t smb = smem_u32(sm);
    float* rowsum = (float*)(sm + RS_B);
    float* invp   = (float*)(sm + INV_B);
    int*   pmp    = (int*)(sm + PM_B);

    const float* Qb = Q + ((size_t)bh * Sdim + q0) * Ddim;
    const int*   pb = pad + (size_t)b * Sdim;
    const char*  Gkv = (const char*)g_kv + (size_t)bh * NSLAB * SLAB_B;
    float* Wb = outW + ((size_t)bh * Sdim + q0) * Sdim;

    // ---- prologue: stage Q*0.125 (fp16 hi/lo), kick slab-0, pad[0] ----
    for (int i = tid; i < TQ * Ddim / 4; i += 256) {
        int q = i >> 4, db = (i & 15) * 4;
        float4 v = *(const float4*)(Qb + (size_t)q * Ddim + db);
        v.x *= 0.125f; v.y *= 0.125f; v.z *= 0.125f; v.w *= 0.125f;
        int base = q * TSTR + db * 2;
        split2h(sm + QS_HI_B, sm + QS_LO_B, base,     v.x, v.y);
        split2h(sm + QS_HI_B, sm + QS_LO_B, base + 4, v.z, v.w);
    }
    for (int i = tid; i < SLAB_B / 16; i += 256)
        cp16(smb + KV0_B + i * 16, Gkv + i * 16);
    asm volatile("cp.async.commit_group;" ::: "memory");
    if (tid < NK) pmp[tid] = pb[tid];
    if (tid < TQ) rowsum[tid] = 0.f;
    __syncthreads();

    const int wq = wid & 3;
    const int wk = wid >> 2;
    const int arow  = lane & 15;
    const int apart = (lane >> 4) * 16;
    const int brow  = (lane & 7) + ((lane >> 4) << 3);
    const int bpart = ((lane >> 3) & 1) * 16;
    const int vrow  = (lane & 7) + (((lane >> 3) & 1) << 3);
    const int vpart = (lane >> 4) * 16;
    const int rlo = wq * 16 + (lane >> 2);
    float rs_lo = 0.f, rs_hi = 0.f;

    // hoist Q A-fragments (hi and lo; both used in 2-pass QK)
    uint32_t aH[4][4], aL[4][4];
    #pragma unroll
    for (int ks = 0; ks < 4; ++ks) {
        ldsm4(smb + QS_HI_B + (wq * 16 + arow) * TSTR + ks * 32 + apart,
              aH[ks][0], aH[ks][1], aH[ks][2], aH[ks][3]);
        ldsm4(smb + QS_LO_B + (wq * 16 + arow) * TSTR + ks * 32 + apart,
              aL[ks][0], aL[ks][1], aL[ks][2], aL[ks][3]);
    }

    float co[4][4];
    #pragma unroll
    for (int n = 0; n < 4; ++n)
        #pragma unroll
        for (int j = 0; j < 4; ++j) co[n][j] = 0.f;

    const int qglo = q0 + rlo, qghi = qglo + 8;

    // ======================= mainloop =======================
    for (int s = 0; s < NSLAB; ++s) {
        const int buf = s & 1;
        const uint32_t KV = smb + KV0_B + buf * SLAB_B;   // K_hi at 0, V_hi at +TILE_B

        asm volatile("cp.async.wait_group 0;" ::: "memory");
        __syncthreads();

        // kick next slab copy + pad mask
        if (s + 1 < NSLAB) {
            const char* gsrc = Gkv + (size_t)(s + 1) * SLAB_B;
            const uint32_t sdst = smb + KV0_B + (buf ^ 1) * SLAB_B;
            for (int i = tid; i < SLAB_B / 16; i += 256)
                cp16(sdst + i * 16, gsrc + i * 16);
            asm volatile("cp.async.commit_group;" ::: "memory");
            if (tid < NK) pmp[(buf ^ 1) * 64 + tid] = pb[(s + 1) * NK + tid];
        }

        // ---- QK^T(s): 2 passes (Qhi*Khi + Qlo*Khi), K_hi loaded once ----
        float c[4][4];
        #pragma unroll
        for (int n = 0; n < 4; ++n)
            #pragma unroll
            for (int j = 0; j < 4; ++j) c[n][j] = 0.f;

        #pragma unroll
        for (int ks = 0; ks < 4; ++ks) {
            #pragma unroll
            for (int nt2 = 0; nt2 < 2; ++nt2) {
                const uint32_t boff = (wk * 32 + nt2 * 16 + brow) * TSTR + ks * 32 + bpart;
                uint32_t h0, h1, h2, h3;
                ldsm4(KV + boff, h0, h1, h2, h3);   // K_hi
                mma16816(c[2 * nt2],     aH[ks][0], aH[ks][1], aH[ks][2], aH[ks][3], h0, h1);
                mma16816(c[2 * nt2 + 1], aH[ks][0], aH[ks][1], aH[ks][2], aH[ks][3], h2, h3);
                mma16816(c[2 * nt2],     aL[ks][0], aL[ks][1], aL[ks][2], aL[ks][3], h0, h1);
                mma16816(c[2 * nt2 + 1], aL[ks][0], aL[ks][1], aL[ks][2], aL[ks][3], h2, h3);
            }
        }

        // ---- epilogue(s): mask/exp (scale pre-folded), rowsum, W store, split -> PS ----
        const int* pmb = pmp + buf * 64;
        const int k0 = s * NK;
        #pragma unroll
        for (int nt = 0; nt < 4; ++nt) {
            const int col = wk * 32 + nt * 8 + (lane & 3) * 2;
            const int kg  = k0 + col;
            const int p0 = pmb[col], p1 = pmb[col + 1];
            float e0 = (((kg     > qglo) + p0) == 1) ? 0.f : __expf(c[nt][0]);
            float e1 = (((kg + 1 > qglo) + p1) == 1) ? 0.f : __expf(c[nt][1]);
            float e2 = (((kg     > qghi) + p0) == 1) ? 0.f : __expf(c[nt][2]);
            float e3 = (((kg + 1 > qghi) + p1) == 1) ? 0.f : __expf(c[nt][3]);
            rs_lo += e0 + e1;
            rs_hi += e2 + e3;
            __stcs((float2*)&Wb[(size_t)rlo * Sdim + kg],       make_float2(e0, e1));
            __stcs((float2*)&Wb[(size_t)(rlo + 8) * Sdim + kg], make_float2(e2, e3));
            split2h(sm + PS_HI_B, sm + PS_LO_B, rlo * TSTR + col * 2,       e0, e1);
            split2h(sm + PS_HI_B, sm + PS_LO_B, (rlo + 8) * TSTR + col * 2, e2, e3);
        }
        __syncthreads();   // PS columns span both wk warps

        // ---- PV(s): 2 passes (Phi*Vhi + Plo*Vhi), V_hi loaded once ----
        #pragma unroll
        for (int ks = 0; ks < 4; ++ks) {
            const uint32_t aoff = (wq * 16 + arow) * TSTR + ks * 32 + apart;
            uint32_t pH[4], pL[4];
            ldsm4(smb + PS_HI_B + aoff, pH[0], pH[1], pH[2], pH[3]);
            ldsm4(smb + PS_LO_B + aoff, pL[0], pL[1], pL[2], pL[3]);
            #pragma unroll
            for (int nt2 = 0; nt2 < 2; ++nt2) {
                const uint32_t voff = (ks * 16 + vrow) * TSTR + (wk * 32 + nt2 * 16) * 2 + vpart;
                uint32_t h0, h1, h2, h3;
                ldsm4t(KV + TILE_B + voff, h0, h1, h2, h3);   // V_hi
                mma16816(co[2 * nt2],     pH[0], pH[1], pH[2], pH[3], h0, h1);
                mma16816(co[2 * nt2 + 1], pH[0], pH[1], pH[2], pH[3], h2, h3);
                mma16816(co[2 * nt2],     pL[0], pL[1], pL[2], pL[3], h0, h1);
                mma16816(co[2 * nt2 + 1], pL[0], pL[1], pL[2], pL[3], h2, h3);
            }
        }
    }

    // ---- rowsums -> inv ----
    rs_lo += __shfl_xor_sync(0xffffffffu, rs_lo, 1);
    rs_lo += __shfl_xor_sync(0xffffffffu, rs_lo, 2);
    rs_hi += __shfl_xor_sync(0xffffffffu, rs_hi, 1);
    rs_hi += __shfl_xor_sync(0xffffffffu, rs_hi, 2);
    if ((lane & 3) == 0) {
        atomicAdd(&rowsum[rlo], rs_lo);
        atomicAdd(&rowsum[rlo + 8], rs_hi);
    }
    __syncthreads();
    if (tid < TQ) invp[tid] = 1.0f / rowsum[tid];
    __syncthreads();

    // ---- O store (normalize accumulators) ----
    {
        const float ivlo = invp[rlo], ivhi = invp[rlo + 8];
        #pragma unroll
        for (int nt = 0; nt < 4; ++nt) {
            const int col = wk * 32 + nt * 8 + (lane & 3) * 2;
            const size_t r0o = ((size_t)bh * Sdim + q0 + rlo) * Ddim + col;
            const size_t r1o = ((size_t)bh * Sdim + q0 + rlo + 8) * Ddim + col;
            *(float2*)&outO[r0o] = make_float2(co[nt][0] * ivlo, co[nt][1] * ivlo);
            *(float2*)&outO[r1o] = make_float2(co[nt][2] * ivhi, co[nt][3] * ivhi);
        }
    }

    // ---- W normalize sweep (streaming) ----
    for (int i = tid; i < TQ * (Sdim / 4); i += 256) {
        int q = i >> 9, c4 = (i & 511) * 4;
        float* gw = Wb + (size_t)q * Sdim + c4;
        float4 e = __ldcs((const float4*)gw);
        const float iv = invp[q];
        e.x *= iv; e.y *= iv; e.z *= iv; e.w *= iv;
        __stcs((float4*)gw, e);
    }
}

extern "C" void kernel_launch(void* const* d_in, const int* in_sizes, int n_in,
                              void* d_out, int out_size)
{
    const float* Q   = (const float*)d_in[0];
    const float* K   = (const float*)d_in[1];
    const float* V   = (const float*)d_in[2];
    const int*   pad = (const int*)d_in[3];

    const long long nres = (long long)BHdim * Sdim * Ddim;
    float* outO = (float*)d_out;
    float* outW = outO + nres;   // out = (result, attention_weights)

    dim3 pgrid(NSLAB, BHdim);
    prep_kv<<<pgrid, 256>>>(K, V);

    cudaFuncSetAttribute(attn_fused, cudaFuncAttributeMaxDynamicSharedMemorySize, SMEM_TOTAL);
    dim3 grid(Sdim / TQ, BHdim);
    attn_fused<<<grid, 256, SMEM_TOTAL>>>(Q, pad, outO, outW);
}

// round 14
// speedup vs baseline: 1.3304x; 1.1853x over previous
#include <cuda_runtime.h>
#include <cuda_fp16.h>
#include <stdint.h>

// ---------------- problem constants ----------------
constexpr int Sdim = 2048, Hdim = 16, BHdim = 64, Ddim = 64;
constexpr int TQ = 16;            // query rows per CTA (one MMA M-tile)
constexpr int NK = 64;            // key slab
constexpr int NSLAB = Sdim / NK;  // 32

constexpr int TSTR = 144;         // bytes per fp16 K/V/Q tile row (64+8 elems)
constexpr int TILE_B = NK * TSTR;            // 9216
constexpr int SLAB_B = 2 * TILE_B;           // K | V (fp16) = 18432
__device__ __align__(16) unsigned char g_kv[(size_t)BHdim * NSLAB * SLAB_B];

// ---------------- smem layout (byte offsets) ----------------
constexpr int SSTR    = 4112;     // strip row stride: 2048+8 halfs (odd 16B units -> conflict-free)
constexpr int RS_B    = 0;        // f32[16]
constexpr int INV_B   = 64;       // f32[16]
constexpr int PM_B    = 128;      // int[2][64]
constexpr int QS_HI_B = 1024;     // [16][72] fp16 = 2304 each
constexpr int QS_LO_B = 3328;
constexpr int KV0_B   = 5632;     // double-buffered slab: 2 x 18432 -> end 42496
constexpr int STRIP_B = 42496;    // fp16 [16][2056] = 65792
constexpr int SMEM_TOTAL = 108288;   // x2 CTAs = 216,576 B

// ---------------- helpers ----------------
__device__ __forceinline__ uint32_t smem_u32(const void* p) {
    uint32_t a;
    asm("{ .reg .u64 t; cvta.to.shared.u64 t, %1; cvt.u32.u64 %0, t; }" : "=r"(a) : "l"(p));
    return a;
}
__device__ __forceinline__ void cp16(uint32_t sdst, const void* gsrc) {
    asm volatile("cp.async.cg.shared.global [%0], [%1], 16;" :: "r"(sdst), "l"(gsrc));
}
__device__ __forceinline__ void ldsm4(uint32_t addr, uint32_t& r0, uint32_t& r1,
                                      uint32_t& r2, uint32_t& r3) {
    asm volatile("ldmatrix.sync.aligned.m8n8.x4.shared.b16 {%0,%1,%2,%3}, [%4];"
                 : "=r"(r0), "=r"(r1), "=r"(r2), "=r"(r3) : "r"(addr));
}
__device__ __forceinline__ void ldsm4t(uint32_t addr, uint32_t& r0, uint32_t& r1,
                                       uint32_t& r2, uint32_t& r3) {
    asm volatile("ldmatrix.sync.aligned.m8n8.x4.trans.shared.b16 {%0,%1,%2,%3}, [%4];"
                 : "=r"(r0), "=r"(r1), "=r"(r2), "=r"(r3) : "r"(addr));
}
__device__ __forceinline__ void mma16816(float* c, uint32_t a0, uint32_t a1,
                                         uint32_t a2, uint32_t a3,
                                         uint32_t b0, uint32_t b1) {
    asm volatile(
        "mma.sync.aligned.m16n8k16.row.col.f32.f16.f16.f32 "
        "{%0,%1,%2,%3}, {%4,%5,%6,%7}, {%8,%9}, {%0,%1,%2,%3};"
        : "+f"(c[0]), "+f"(c[1]), "+f"(c[2]), "+f"(c[3])
        : "r"(a0), "r"(a1), "r"(a2), "r"(a3), "r"(b0), "r"(b1));
}
__device__ __forceinline__ void split2h(char* hiB, char* loB, int off, float a, float b) {
    __half ah = __float2half_rn(a);
    __half bh = __float2half_rn(b);
    __half al = __float2half_rn(a - __half2float(ah));
    __half bl = __float2half_rn(b - __half2float(bh));
    *(__half2*)(hiB + off) = __halves2half2(ah, bh);
    *(__half2*)(loB + off) = __halves2half2(al, bl);
}
__device__ __forceinline__ void cvt2h(char* dst, int off, float a, float b) {
    *(__half2*)(dst + off) = __halves2half2(__float2half_rn(a), __float2half_rn(b));
}

// ================= preprocessing: K,V fp32 -> tiled fp16 =================
__global__ __launch_bounds__(256)
void prep_kv(const float* __restrict__ K, const float* __restrict__ V)
{
    const int s  = blockIdx.x;
    const int bh = blockIdx.y;
    const int tid = threadIdx.x;
    const float* Kb = K + ((size_t)bh * Sdim + s * NK) * Ddim;
    const float* Vb = V + ((size_t)bh * Sdim + s * NK) * Ddim;
    char* dst = (char*)g_kv + ((size_t)bh * NSLAB + s) * SLAB_B;

    for (int i = tid; i < NK * Ddim / 4; i += 256) {
        int k = i >> 4, db = (i & 15) * 4;
        int off = k * TSTR + db * 2;
        float4 kv4 = *(const float4*)(Kb + (size_t)k * Ddim + db);
        cvt2h(dst, off,     kv4.x, kv4.y);
        cvt2h(dst, off + 4, kv4.z, kv4.w);
        float4 vv4 = *(const float4*)(Vb + (size_t)k * Ddim + db);
        cvt2h(dst + TILE_B, off,     vv4.x, vv4.y);
        cvt2h(dst + TILE_B, off + 4, vv4.z, vv4.w);
    }
}

// ================= fused attention: smem-resident e-strip, single W write ============
__global__ __launch_bounds__(256, 2)
void attn_fused(const float* __restrict__ Q, const int* __restrict__ pad,
                float* __restrict__ outO, float* __restrict__ outW)
{
    extern __shared__ __align__(16) char sm[];
    const int tid  = threadIdx.x;
    const int wid  = tid >> 5;     // 8 warps; each owns 8 k-cols (QK) / 8 d-cols (PV)
    const int lane = tid & 31;
    const int bh   = blockIdx.y;
    const int q0   = blockIdx.x * TQ;
    const int b    = bh / Hdim;

    const uint32_t smb = smem_u32(sm);
    float* rowsum = (float*)(sm + RS_B);
    float* invp   = (float*)(sm + INV_B);
    int*   pmp    = (int*)(sm + PM_B);   // [2][64]

    const float* Qb = Q + ((size_t)bh * Sdim + q0) * Ddim;
    const int*   pb = pad + (size_t)b * Sdim;
    const char*  Gkv = (const char*)g_kv + (size_t)bh * NSLAB * SLAB_B;
    float* Wb = outW + ((size_t)bh * Sdim + q0) * Sdim;   // [TQ][Sdim]

    // ---- prologue: stage Q*0.125 (fp16 hi/lo), kick slab-0, pad[0] ----
    if (tid < TQ * Ddim / 4) {   // 256 float4 == one per thread
        int q = tid >> 4, db = (tid & 15) * 4;
        float4 v = *(const float4*)(Qb + (size_t)q * Ddim + db);
        v.x *= 0.125f; v.y *= 0.125f; v.z *= 0.125f; v.w *= 0.125f;
        int base = q * TSTR + db * 2;
        split2h(sm + QS_HI_B, sm + QS_LO_B, base,     v.x, v.y);
        split2h(sm + QS_HI_B, sm + QS_LO_B, base + 4, v.z, v.w);
    }
    for (int i = tid; i < SLAB_B / 16; i += 256)
        cp16(smb + KV0_B + i * 16, Gkv + i * 16);
    asm volatile("cp.async.commit_group;" ::: "memory");
    if (tid < NK) pmp[tid] = pb[tid];
    if (tid < TQ) rowsum[tid] = 0.f;
    __syncthreads();

    // fragment address components
    const int arow  = lane & 15;              // A rows (Q / P)
    const int apart = (lane >> 4) * 16;
    const int krow  = wid * 8 + (lane & 7);   // K B-frag: warp's 8 cols
    const int kpart = (lane >> 3) * 16;       // covers k elems 0..31 (2 ks) per ldsm4
    const int vr    = (lane & 7) + (lane >> 3) * 8;   // V trans: 32 k-rows per ldsm4t
    const int rlo   = lane >> 2;              // output rows rlo, rlo+8
    float rs_lo = 0.f, rs_hi = 0.f;

    // hoist Q A-fragments (hi and lo)
    uint32_t aH[4][4], aL[4][4];
    #pragma unroll
    for (int ks = 0; ks < 4; ++ks) {
        ldsm4(smb + QS_HI_B + arow * TSTR + ks * 32 + apart,
              aH[ks][0], aH[ks][1], aH[ks][2], aH[ks][3]);
        ldsm4(smb + QS_LO_B + arow * TSTR + ks * 32 + apart,
              aL[ks][0], aL[ks][1], aL[ks][2], aL[ks][3]);
    }

    float co[4] = {0.f, 0.f, 0.f, 0.f};
    const int qglo = q0 + rlo, qghi = qglo + 8;

    // ======================= mainloop =======================
    for (int s = 0; s < NSLAB; ++s) {
        const int buf = s & 1;
        const uint32_t KV = smb + KV0_B + buf * SLAB_B;   // K at 0, V at +TILE_B
        const int k0 = s * NK;

        asm volatile("cp.async.wait_group 0;" ::: "memory");
        __syncthreads();   // slab s visible; PV(s-1) readers of buf^1 done

        // kick next slab + pad mask into buf^1
        if (s + 1 < NSLAB) {
            const char* gsrc = Gkv + (size_t)(s + 1) * SLAB_B;
            const uint32_t sdst = smb + KV0_B + (buf ^ 1) * SLAB_B;
            for (int i = tid; i < SLAB_B / 16; i += 256)
                cp16(sdst + i * 16, gsrc + i * 16);
            asm volatile("cp.async.commit_group;" ::: "memory");
            if (tid < NK) pmp[(buf ^ 1) * 64 + tid] = pb[(s + 1) * NK + tid];
        }

        // ---- QK^T(s): 2 passes (Qhi + Qlo) x K, 8 MMAs into one n8 tile ----
        float c[4] = {0.f, 0.f, 0.f, 0.f};
        {
            uint32_t bA[4], bB[4];
            const uint32_t kaddr = KV + krow * TSTR + kpart;
            ldsm4(kaddr,      bA[0], bA[1], bA[2], bA[3]);   // ks0, ks1
            ldsm4(kaddr + 64, bB[0], bB[1], bB[2], bB[3]);   // ks2, ks3
            mma16816(c, aH[0][0], aH[0][1], aH[0][2], aH[0][3], bA[0], bA[1]);
            mma16816(c, aL[0][0], aL[0][1], aL[0][2], aL[0][3], bA[0], bA[1]);
            mma16816(c, aH[1][0], aH[1][1], aH[1][2], aH[1][3], bA[2], bA[3]);
            mma16816(c, aL[1][0], aL[1][1], aL[1][2], aL[1][3], bA[2], bA[3]);
            mma16816(c, aH[2][0], aH[2][1], aH[2][2], aH[2][3], bB[0], bB[1]);
            mma16816(c, aL[2][0], aL[2][1], aL[2][2], aL[2][3], bB[0], bB[1]);
            mma16816(c, aH[3][0], aH[3][1], aH[3][2], aH[3][3], bB[2], bB[3]);
            mma16816(c, aL[3][0], aL[3][1], aL[3][2], aL[3][3], bB[2], bB[3]);
        }

        // ---- epilogue(s): mask/exp, rowsum, e -> strip (fp16) ----
        {
            const int* pmb = pmp + buf * 64;
            const int col = wid * 8 + (lane & 3) * 2;
            const int kg  = k0 + col;
            const int p0 = pmb[col], p1 = pmb[col + 1];
            float e0 = (((kg     > qglo) + p0) == 1) ? 0.f : __expf(c[0]);
            float e1 = (((kg + 1 > qglo) + p1) == 1) ? 0.f : __expf(c[1]);
            float e2 = (((kg     > qghi) + p0) == 1) ? 0.f : __expf(c[2]);
            float e3 = (((kg + 1 > qghi) + p1) == 1) ? 0.f : __expf(c[3]);
            rs_lo += e0 + e1;
            rs_hi += e2 + e3;
            *(__half2*)(sm + STRIP_B + rlo * SSTR + kg * 2) =
                __halves2half2(__float2half_rn(e0), __float2half_rn(e1));
            *(__half2*)(sm + STRIP_B + (rlo + 8) * SSTR + kg * 2) =
                __halves2half2(__float2half_rn(e2), __float2half_rn(e3));
        }
        __syncthreads();   // strip cols of slab s complete (cross-warp reads in PV)

        // ---- PV(s): single-pass fp16, P from strip, V from slab ----
        {
            uint32_t vA[4], vB[4];
            const uint32_t vaddr = KV + TILE_B + vr * TSTR + wid * 16;
            ldsm4t(vaddr,            vA[0], vA[1], vA[2], vA[3]);   // k 0..31
            ldsm4t(vaddr + 32 * TSTR, vB[0], vB[1], vB[2], vB[3]);  // k 32..63
            #pragma unroll
            for (int ks = 0; ks < 4; ++ks) {
                uint32_t a0, a1, a2, a3;
                ldsm4(smb + STRIP_B + arow * SSTR + (k0 + ks * 16) * 2 + apart,
                      a0, a1, a2, a3);
                const uint32_t* vv = (ks < 2) ? vA : vB;
                mma16816(co, a0, a1, a2, a3, vv[(ks & 1) * 2], vv[(ks & 1) * 2 + 1]);
            }
        }
    }

    // ---- rowsums -> inv ----
    rs_lo += __shfl_xor_sync(0xffffffffu, rs_lo, 1);
    rs_lo += __shfl_xor_sync(0xffffffffu, rs_lo, 2);
    rs_hi += __shfl_xor_sync(0xffffffffu, rs_hi, 1);
    rs_hi += __shfl_xor_sync(0xffffffffu, rs_hi, 2);
    if ((lane & 3) == 0) {
        atomicAdd(&rowsum[rlo], rs_lo);
        atomicAdd(&rowsum[rlo + 8], rs_hi);
    }
    __syncthreads();
    if (tid < TQ) invp[tid] = 1.0f / rowsum[tid];
    __syncthreads();

    // ---- W write (single pass, normalized, coalesced from strip) ----
    for (int i = tid; i < TQ * (Sdim / 4); i += 256) {   // 8192 float4 stores
        int q = i >> 9, c4 = (i & 511) * 4;
        const uint32_t* sp = (const uint32_t*)(sm + STRIP_B + q * SSTR + c4 * 2);
        uint32_t u0 = sp[0], u1 = sp[1];
        float2 lo = __half22float2(*(__half2*)&u0);
        float2 hi = __half22float2(*(__half2*)&u1);
        const float iv = invp[q];
        float4 w = make_float4(lo.x * iv, lo.y * iv, hi.x * iv, hi.y * iv);
        __stcs((float4*)&Wb[(size_t)q * Sdim + c4], w);
    }

    // ---- O store (normalize accumulators) ----
    {
        const float ivlo = invp[rlo], ivhi = invp[rlo + 8];
        const int col = wid * 8 + (lane & 3) * 2;
        const size_t r0o = ((size_t)bh * Sdim + q0 + rlo) * Ddim + col;
        const size_t r1o = ((size_t)bh * Sdim + q0 + rlo + 8) * Ddim + col;
        *(float2*)&outO[r0o] = make_float2(co[0] * ivlo, co[1] * ivlo);
        *(float2*)&outO[r1o] = make_float2(co[2] * ivhi, co[3] * ivhi);
    }
}

extern "C" void kernel_launch(void* const* d_in, const int* in_sizes, int n_in,
                              void* d_out, int out_size)
{
    const float* Q   = (const float*)d_in[0];
    const float* K   = (const float*)d_in[1];
    const float* V   = (const float*)d_in[2];
    const int*   pad = (const int*)d_in[3];

    const long long nres = (long long)BHdim * Sdim * Ddim;
    float* outO = (float*)d_out;
    float* outW = outO + nres;   // out = (result, attention_weights)

    dim3 pgrid(NSLAB, BHdim);
    prep_kv<<<pgrid, 256>>>(K, V);

    cudaFuncSetAttribute(attn_fused, cudaFuncAttributeMaxDynamicSharedMemorySize, SMEM_TOTAL);
    dim3 grid(Sdim / TQ, BHdim);
    attn_fused<<<grid, 256, SMEM_TOTAL>>>(Q, pad, outO, outW);
}

// round 15
// speedup vs baseline: 1.7233x; 1.2953x over previous
#include <cuda_runtime.h>
#include <cuda_fp16.h>
#include <stdint.h>

// ---------------- problem constants ----------------
constexpr int Sdim = 2048, Hdim = 16, BHdim = 64, Ddim = 64;
constexpr int TQ = 16;            // query rows per CTA (one MMA M-tile)
constexpr int NK = 128;           // key slab (8 warps x 16 k-cols)
constexpr int NSLAB = Sdim / NK;  // 16

constexpr int TSTR = 144;         // bytes per fp16 K/V/Q tile row (64+8 elems)
constexpr int TILE_B = NK * TSTR;            // 18432 (one K or V tile)
constexpr int SLAB_B = 2 * TILE_B;           // K | V = 36864
__device__ __align__(16) unsigned char g_kv[(size_t)BHdim * NSLAB * SLAB_B];

// ---------------- smem layout (byte offsets) ----------------
constexpr int SSTR    = 4112;     // strip row stride bytes (2048+8 halfs)
constexpr int RS_B    = 0;        // f32[16]
constexpr int INV_B   = 64;       // f32[16]
constexpr int PM_B    = 128;      // int[2][128]
constexpr int QS_HI_B = 1152;     // [16][72] fp16 = 2304 each
constexpr int QS_LO_B = 3456;
constexpr int K_B     = 5760;     // K tile 18432 (single buffer, in-place refresh)
constexpr int V_B     = 24192;    // V tile 18432
constexpr int STRIP_B = 42624;    // fp16 [16][2056] = 65792
constexpr int SMEM_TOTAL = 108416;   // x2 CTAs fits 228KB SM
constexpr int COSM_B  = K_B;      // reused after mainloop: f32 [8][16][68] = 34816

// ---------------- helpers ----------------
__device__ __forceinline__ uint32_t smem_u32(const void* p) {
    uint32_t a;
    asm("{ .reg .u64 t; cvta.to.shared.u64 t, %1; cvt.u32.u64 %0, t; }" : "=r"(a) : "l"(p));
    return a;
}
__device__ __forceinline__ void cp16(uint32_t sdst, const void* gsrc) {
    asm volatile("cp.async.cg.shared.global [%0], [%1], 16;" :: "r"(sdst), "l"(gsrc));
}
__device__ __forceinline__ void ldsm4(uint32_t addr, uint32_t& r0, uint32_t& r1,
                                      uint32_t& r2, uint32_t& r3) {
    asm volatile("ldmatrix.sync.aligned.m8n8.x4.shared.b16 {%0,%1,%2,%3}, [%4];"
                 : "=r"(r0), "=r"(r1), "=r"(r2), "=r"(r3) : "r"(addr));
}
__device__ __forceinline__ void ldsm4t(uint32_t addr, uint32_t& r0, uint32_t& r1,
                                       uint32_t& r2, uint32_t& r3) {
    asm volatile("ldmatrix.sync.aligned.m8n8.x4.trans.shared.b16 {%0,%1,%2,%3}, [%4];"
                 : "=r"(r0), "=r"(r1), "=r"(r2), "=r"(r3) : "r"(addr));
}
__device__ __forceinline__ void mma16816(float* c, uint32_t a0, uint32_t a1,
                                         uint32_t a2, uint32_t a3,
                                         uint32_t b0, uint32_t b1) {
    asm volatile(
        "mma.sync.aligned.m16n8k16.row.col.f32.f16.f16.f32 "
        "{%0,%1,%2,%3}, {%4,%5,%6,%7}, {%8,%9}, {%0,%1,%2,%3};"
        : "+f"(c[0]), "+f"(c[1]), "+f"(c[2]), "+f"(c[3])
        : "r"(a0), "r"(a1), "r"(a2), "r"(a3), "r"(b0), "r"(b1));
}
__device__ __forceinline__ void split2h(char* hiB, char* loB, int off, float a, float b) {
    __half ah = __float2half_rn(a);
    __half bh = __float2half_rn(b);
    __half al = __float2half_rn(a - __half2float(ah));
    __half bl = __float2half_rn(b - __half2float(bh));
    *(__half2*)(hiB + off) = __halves2half2(ah, bh);
    *(__half2*)(loB + off) = __halves2half2(al, bl);
}
__device__ __forceinline__ void cvt2h(char* dst, int off, float a, float b) {
    *(__half2*)(dst + off) = __halves2half2(__float2half_rn(a), __float2half_rn(b));
}
__device__ __forceinline__ uint32_t packh(float a, float b) {
    __half2 h = __halves2half2(__float2half_rn(a), __float2half_rn(b));
    return *(uint32_t*)&h;
}

// ================= preprocessing: K,V fp32 -> tiled fp16 =================
__global__ __launch_bounds__(256)
void prep_kv(const float* __restrict__ K, const float* __restrict__ V)
{
    const int s  = blockIdx.x;
    const int bh = blockIdx.y;
    const int tid = threadIdx.x;
    const float* Kb = K + ((size_t)bh * Sdim + s * NK) * Ddim;
    const float* Vb = V + ((size_t)bh * Sdim + s * NK) * Ddim;
    char* dst = (char*)g_kv + ((size_t)bh * NSLAB + s) * SLAB_B;

    for (int i = tid; i < NK * Ddim / 4; i += 256) {   // 2048 float4 each
        int k = i >> 4, db = (i & 15) * 4;
        int off = k * TSTR + db * 2;
        float4 kv4 = *(const float4*)(Kb + (size_t)k * Ddim + db);
        cvt2h(dst, off,     kv4.x, kv4.y);
        cvt2h(dst, off + 4, kv4.z, kv4.w);
        float4 vv4 = *(const float4*)(Vb + (size_t)k * Ddim + db);
        cvt2h(dst + TILE_B, off,     vv4.x, vv4.y);
        cvt2h(dst + TILE_B, off + 4, vv4.z, vv4.w);
    }
}

// ================= fused attention: warp-local PV, register A-fragments ============
__global__ __launch_bounds__(256, 2)
void attn_fused(const float* __restrict__ Q, const int* __restrict__ pad,
                float* __restrict__ outO, float* __restrict__ outW)
{
    extern __shared__ __align__(16) char sm[];
    const int tid  = threadIdx.x;
    const int wid  = tid >> 5;     // warp owns k-cols wid*16..+15 of each slab
    const int lane = tid & 31;
    const int bh   = blockIdx.y;
    const int q0   = blockIdx.x * TQ;
    const int b    = bh / Hdim;

    const uint32_t smb = smem_u32(sm);
    float* rowsum = (float*)(sm + RS_B);
    float* invp   = (float*)(sm + INV_B);
    int*   pmp    = (int*)(sm + PM_B);   // [2][128]

    const float* Qb = Q + ((size_t)bh * Sdim + q0) * Ddim;
    const int*   pb = pad + (size_t)b * Sdim;
    const char*  Gkv = (const char*)g_kv + (size_t)bh * NSLAB * SLAB_B;
    float* Wb = outW + ((size_t)bh * Sdim + q0) * Sdim;   // [TQ][Sdim]

    // ---- prologue: stage Q*0.125 (fp16 hi/lo); issue K(0), V(0); pad[0] ----
    if (tid < TQ * Ddim / 4) {
        int q = tid >> 4, db = (tid & 15) * 4;
        float4 v = *(const float4*)(Qb + (size_t)q * Ddim + db);
        v.x *= 0.125f; v.y *= 0.125f; v.z *= 0.125f; v.w *= 0.125f;
        int base = q * TSTR + db * 2;
        split2h(sm + QS_HI_B, sm + QS_LO_B, base,     v.x, v.y);
        split2h(sm + QS_HI_B, sm + QS_LO_B, base + 4, v.z, v.w);
    }
    for (int i = tid; i < TILE_B / 16; i += 256)      // K(0)
        cp16(smb + K_B + i * 16, Gkv + i * 16);
    asm volatile("cp.async.commit_group;" ::: "memory");
    for (int i = tid; i < TILE_B / 16; i += 256)      // V(0)
        cp16(smb + V_B + i * 16, Gkv + TILE_B + i * 16);
    asm volatile("cp.async.commit_group;" ::: "memory");
    if (tid < NK) pmp[tid] = pb[tid];
    if (tid < TQ) rowsum[tid] = 0.f;
    __syncthreads();

    // fragment address components
    const int arow  = lane & 15;
    const int apart = (lane >> 4) * 16;
    const int brow  = (lane & 7) + ((lane >> 4) << 3);      // B (QK, no trans), 16 rows
    const int bpart = ((lane >> 3) & 1) * 16;
    const int vrow  = (lane & 7) + (((lane >> 3) & 1) << 3); // B (PV, trans), 16 rows
    const int vpart = (lane >> 4) * 16;
    const int rlo   = lane >> 2;
    float rs_lo = 0.f, rs_hi = 0.f;

    // hoist Q A-fragments (hi and lo)
    uint32_t aH[4][4], aL[4][4];
    #pragma unroll
    for (int ks = 0; ks < 4; ++ks) {
        ldsm4(smb + QS_HI_B + arow * TSTR + ks * 32 + apart,
              aH[ks][0], aH[ks][1], aH[ks][2], aH[ks][3]);
        ldsm4(smb + QS_LO_B + arow * TSTR + ks * 32 + apart,
              aL[ks][0], aL[ks][1], aL[ks][2], aL[ks][3]);
    }

    // partial-O accumulators: 8 n8 d-tiles (all 64 d-cols), warp's k-slice only
    float co[8][4];
    #pragma unroll
    for (int t = 0; t < 8; ++t)
        #pragma unroll
        for (int j = 0; j < 4; ++j) co[t][j] = 0.f;

    const int qglo = q0 + rlo, qghi = qglo + 8;
    const uint32_t kbase = smb + K_B + (wid * 16 + brow) * TSTR + bpart;
    const uint32_t vbase = smb + V_B + (wid * 16 + vrow) * TSTR + vpart;

    // ======================= mainloop =======================
    // cp group order: K(0),V(0),K(1),V(1),...  wait_group 1 at each consume point.
    for (int s = 0; s < NSLAB; ++s) {
        const int buf = s & 1;
        const int k0 = s * NK;

        // ---- K(s) ready ----
        asm volatile("cp.async.wait_group 1;" ::: "memory");
        __syncthreads();

        // ---- QK^T(s): warp's 16 k-cols = 2 n8 tiles; 2 passes (Qhi+Qlo) ----
        float c[8];
        #pragma unroll
        for (int j = 0; j < 8; ++j) c[j] = 0.f;
        #pragma unroll
        for (int ks = 0; ks < 4; ++ks) {
            uint32_t b0, b1, b2, b3;
            ldsm4(kbase + ks * 32, b0, b1, b2, b3);   // tile0: b0,b1; tile1: b2,b3
            mma16816(c,     aH[ks][0], aH[ks][1], aH[ks][2], aH[ks][3], b0, b1);
            mma16816(c + 4, aH[ks][0], aH[ks][1], aH[ks][2], aH[ks][3], b2, b3);
            mma16816(c,     aL[ks][0], aL[ks][1], aL[ks][2], aL[ks][3], b0, b1);
            mma16816(c + 4, aL[ks][0], aL[ks][1], aL[ks][2], aL[ks][3], b2, b3);
        }
        __syncthreads();   // all warps done reading K(s)

        // refresh K in place with K(s+1) + pad mask (overlapped by epilogue + PV)
        if (s + 1 < NSLAB) {
            const char* gsrc = Gkv + (size_t)(s + 1) * SLAB_B;
            for (int i = tid; i < TILE_B / 16; i += 256)
                cp16(smb + K_B + i * 16, gsrc + i * 16);
            if (tid < NK) pmp[(buf ^ 1) * 128 + tid] = pb[(s + 1) * NK + tid];
        }
        asm volatile("cp.async.commit_group;" ::: "memory");

        // ---- epilogue(s): mask/exp, rowsum, e -> strip + register A-fragments ----
        uint32_t a0, a1, a2, a3;
        {
            const int* pmb = pmp + buf * 128;
            const int col0 = wid * 16 + (lane & 3) * 2;   // tile0 cols
            const int col1 = col0 + 8;                    // tile1 cols
            const int kg0 = k0 + col0, kg1 = k0 + col1;
            const int p00 = pmb[col0], p01 = pmb[col0 + 1];
            const int p10 = pmb[col1], p11 = pmb[col1 + 1];
            float e0 = (((kg0     > qglo) + p00) == 1) ? 0.f : __expf(c[0]);
            float e1 = (((kg0 + 1 > qglo) + p01) == 1) ? 0.f : __expf(c[1]);
            float e2 = (((kg0     > qghi) + p00) == 1) ? 0.f : __expf(c[2]);
            float e3 = (((kg0 + 1 > qghi) + p01) == 1) ? 0.f : __expf(c[3]);
            float e4 = (((kg1     > qglo) + p10) == 1) ? 0.f : __expf(c[4]);
            float e5 = (((kg1 + 1 > qglo) + p11) == 1) ? 0.f : __expf(c[5]);
            float e6 = (((kg1     > qghi) + p10) == 1) ? 0.f : __expf(c[6]);
            float e7 = (((kg1 + 1 > qghi) + p11) == 1) ? 0.f : __expf(c[7]);
            rs_lo += (e0 + e1) + (e4 + e5);
            rs_hi += (e2 + e3) + (e6 + e7);
            // A-fragment for PV k16 (warp-local): a0=(r,k),a1=(r+8,k),a2=(r,k+8),a3=(r+8,k+8)
            a0 = packh(e0, e1); a1 = packh(e2, e3);
            a2 = packh(e4, e5); a3 = packh(e6, e7);
            // strip (fp16, same rounding) for final W write
            char* srow0 = sm + STRIP_B + rlo * SSTR;
            char* srow1 = sm + STRIP_B + (rlo + 8) * SSTR;
            *(uint32_t*)(srow0 + kg0 * 2) = a0;
            *(uint32_t*)(srow1 + kg0 * 2) = a1;
            *(uint32_t*)(srow0 + kg1 * 2) = a2;
            *(uint32_t*)(srow1 + kg1 * 2) = a3;
        }

        // ---- V(s) ready ----
        asm volatile("cp.async.wait_group 1;" ::: "memory");
        __syncthreads();

        // ---- PV(s): warp-local k16, all 64 d-cols (8 n8 tiles) ----
        #pragma unroll
        for (int nt = 0; nt < 4; ++nt) {
            uint32_t v0, v1, v2, v3;
            ldsm4t(vbase + nt * 32, v0, v1, v2, v3);
            mma16816(co[2 * nt],     a0, a1, a2, a3, v0, v1);
            mma16816(co[2 * nt + 1], a0, a1, a2, a3, v2, v3);
        }
        __syncthreads();   // all warps done reading V(s)

        // refresh V in place with V(s+1)
        if (s + 1 < NSLAB) {
            const char* gsrc = Gkv + (size_t)(s + 1) * SLAB_B + TILE_B;
            for (int i = tid; i < TILE_B / 16; i += 256)
                cp16(smb + V_B + i * 16, gsrc + i * 16);
        }
        asm volatile("cp.async.commit_group;" ::: "memory");
    }

    // ---- rowsums -> inv ----
    rs_lo += __shfl_xor_sync(0xffffffffu, rs_lo, 1);
    rs_lo += __shfl_xor_sync(0xffffffffu, rs_lo, 2);
    rs_hi += __shfl_xor_sync(0xffffffffu, rs_hi, 1);
    rs_hi += __shfl_xor_sync(0xffffffffu, rs_hi, 2);
    if ((lane & 3) == 0) {
        atomicAdd(&rowsum[rlo], rs_lo);
        atomicAdd(&rowsum[rlo + 8], rs_hi);
    }
    __syncthreads();
    if (tid < TQ) invp[tid] = 1.0f / rowsum[tid];

    // ---- store partial O to smem (reuse K/V region): cosm[w][16][68] f32 ----
    {
        float* cosm = (float*)(sm + COSM_B) + wid * 16 * 68;
        const int dc = (lane & 3) * 2;
        #pragma unroll
        for (int t = 0; t < 8; ++t) {
            *(float2*)&cosm[rlo * 68 + t * 8 + dc]       = make_float2(co[t][0], co[t][1]);
            *(float2*)&cosm[(rlo + 8) * 68 + t * 8 + dc] = make_float2(co[t][2], co[t][3]);
        }
    }
    __syncthreads();

    // ---- W write (single pass, normalized, coalesced from strip) ----
    for (int i = tid; i < TQ * (Sdim / 4); i += 256) {
        int q = i >> 9, c4 = (i & 511) * 4;
        const uint32_t* sp = (const uint32_t*)(sm + STRIP_B + q * SSTR + c4 * 2);
        uint32_t u0 = sp[0], u1 = sp[1];
        float2 lo = __half22float2(*(__half2*)&u0);
        float2 hi = __half22float2(*(__half2*)&u1);
        const float iv = invp[q];
        float4 w = make_float4(lo.x * iv, lo.y * iv, hi.x * iv, hi.y * iv);
        __stcs((float4*)&Wb[(size_t)q * Sdim + c4], w);
    }

    // ---- O reduce across 8 warps + store ----
    {
        const int q = tid >> 4;              // 16 threads per q-row
        const int d = (tid & 15) * 4;
        const float* cosm = (const float*)(sm + COSM_B);
        float4 acc = make_float4(0.f, 0.f, 0.f, 0.f);
        #pragma unroll
        for (int w = 0; w < 8; ++w) {
            float4 t = *(const float4*)&cosm[(w * 16 + q) * 68 + d];
            acc.x += t.x; acc.y += t.y; acc.z += t.z; acc.w += t.w;
        }
        const float iv = invp[q];
        acc.x *= iv; acc.y *= iv; acc.z *= iv; acc.w *= iv;
        *(float4*)&outO[((size_t)bh * Sdim + q0 + q) * Ddim + d] = acc;
    }
}

extern "C" void kernel_launch(void* const* d_in, const int* in_sizes, int n_in,
                              void* d_out, int out_size)
{
    const float* Q   = (const float*)d_in[0];
    const float* K   = (const float*)d_in[1];
    const float* V   = (const float*)d_in[2];
    const int*   pad = (const int*)d_in[3];

    const long long nres = (long long)BHdim * Sdim * Ddim;
    float* outO = (float*)d_out;
    float* outW = outO + nres;   // out = (result, attention_weights)

    dim3 pgrid(NSLAB, BHdim);
    prep_kv<<<pgrid, 256>>>(K, V);

    cudaFuncSetAttribute(attn_fused, cudaFuncAttributeMaxDynamicSharedMemorySize, SMEM_TOTAL);
    dim3 grid(Sdim / TQ, BHdim);
    attn_fused<<<grid, 256, SMEM_TOTAL>>>(Q, pad, outO, outW);
}

// round 16
// speedup vs baseline: 2.0443x; 1.1863x over previous
#include <cuda_runtime.h>
#include <cuda_fp16.h>
#include <stdint.h>
#include <math.h>

// ---------------- problem constants ----------------
constexpr int Sdim = 2048, Hdim = 16, BHdim = 64, Ddim = 64;
constexpr int TQ = 16;            // query rows per CTA (one MMA M-tile)
constexpr int NK = 128;           // key slab (8 warps x 16 k-cols)
constexpr int NSLAB = Sdim / NK;  // 16

constexpr int TSTR = 144;         // bytes per fp16 K/V/Q tile row (64+8 elems)
constexpr int TILE_B = NK * TSTR;            // 18432 (one K or V tile)
constexpr int SLAB_B = 2 * TILE_B;           // K | V = 36864
__device__ __align__(16) unsigned char g_kv[(size_t)BHdim * NSLAB * SLAB_B];

// ---------------- smem layout (byte offsets) ----------------
constexpr int SSTR    = 4112;     // strip row stride bytes (2048+8 halfs)
constexpr int RS_B    = 0;        // f32[16]
constexpr int INV_B   = 64;       // f32[16]
constexpr int PM_B    = 128;      // f32[2][128] pad mask as float
constexpr int QS_HI_B = 1152;     // [16][72] fp16 = 2304 each
constexpr int QS_LO_B = 3456;
constexpr int K_B     = 5760;     // K tile 18432 (single buffer, in-place refresh)
constexpr int V_B     = 24192;    // V tile 18432
constexpr int STRIP_B = 42624;    // fp16 [16][2056] = 65792
constexpr int SMEM_TOTAL = 108416;   // x2 CTAs fits 228KB SM
constexpr int COSM_B  = K_B;      // reused after mainloop: f32 [8][16][68]

// ---------------- helpers ----------------
__device__ __forceinline__ uint32_t smem_u32(const void* p) {
    uint32_t a;
    asm("{ .reg .u64 t; cvta.to.shared.u64 t, %1; cvt.u32.u64 %0, t; }" : "=r"(a) : "l"(p));
    return a;
}
__device__ __forceinline__ void cp16(uint32_t sdst, const void* gsrc) {
    asm volatile("cp.async.cg.shared.global [%0], [%1], 16;" :: "r"(sdst), "l"(gsrc));
}
__device__ __forceinline__ void ldsm4(uint32_t addr, uint32_t& r0, uint32_t& r1,
                                      uint32_t& r2, uint32_t& r3) {
    asm volatile("ldmatrix.sync.aligned.m8n8.x4.shared.b16 {%0,%1,%2,%3}, [%4];"
                 : "=r"(r0), "=r"(r1), "=r"(r2), "=r"(r3) : "r"(addr));
}
__device__ __forceinline__ void ldsm4t(uint32_t addr, uint32_t& r0, uint32_t& r1,
                                       uint32_t& r2, uint32_t& r3) {
    asm volatile("ldmatrix.sync.aligned.m8n8.x4.trans.shared.b16 {%0,%1,%2,%3}, [%4];"
                 : "=r"(r0), "=r"(r1), "=r"(r2), "=r"(r3) : "r"(addr));
}
__device__ __forceinline__ void mma16816(float* c, uint32_t a0, uint32_t a1,
                                         uint32_t a2, uint32_t a3,
                                         uint32_t b0, uint32_t b1) {
    asm volatile(
        "mma.sync.aligned.m16n8k16.row.col.f32.f16.f16.f32 "
        "{%0,%1,%2,%3}, {%4,%5,%6,%7}, {%8,%9}, {%0,%1,%2,%3};"
        : "+f"(c[0]), "+f"(c[1]), "+f"(c[2]), "+f"(c[3])
        : "r"(a0), "r"(a1), "r"(a2), "r"(a3), "r"(b0), "r"(b1));
}
__device__ __forceinline__ void split2h(char* hiB, char* loB, int off, float a, float b) {
    __half ah = __float2half_rn(a);
    __half bh = __float2half_rn(b);
    __half al = __float2half_rn(a - __half2float(ah));
    __half bl = __float2half_rn(b - __half2float(bh));
    *(__half2*)(hiB + off) = __halves2half2(ah, bh);
    *(__half2*)(loB + off) = __halves2half2(al, bl);
}
__device__ __forceinline__ void cvt2h(char* dst, int off, float a, float b) {
    *(__half2*)(dst + off) = __halves2half2(__float2half_rn(a), __float2half_rn(b));
}
__device__ __forceinline__ uint32_t packh(float a, float b) {
    __half2 h = __halves2half2(__float2half_rn(a), __float2half_rn(b));
    return *(uint32_t*)&h;
}

// ================= preprocessing: K,V fp32 -> tiled fp16 =================
__global__ __launch_bounds__(256)
void prep_kv(const float* __restrict__ K, const float* __restrict__ V)
{
    const int s  = blockIdx.x;
    const int bh = blockIdx.y;
    const int tid = threadIdx.x;
    const float* Kb = K + ((size_t)bh * Sdim + s * NK) * Ddim;
    const float* Vb = V + ((size_t)bh * Sdim + s * NK) * Ddim;
    char* dst = (char*)g_kv + ((size_t)bh * NSLAB + s) * SLAB_B;

    for (int i = tid; i < NK * Ddim / 4; i += 256) {
        int k = i >> 4, db = (i & 15) * 4;
        int off = k * TSTR + db * 2;
        float4 kv4 = *(const float4*)(Kb + (size_t)k * Ddim + db);
        cvt2h(dst, off,     kv4.x, kv4.y);
        cvt2h(dst, off + 4, kv4.z, kv4.w);
        float4 vv4 = *(const float4*)(Vb + (size_t)k * Ddim + db);
        cvt2h(dst + TILE_B, off,     vv4.x, vv4.y);
        cvt2h(dst + TILE_B, off + 4, vv4.z, vv4.w);
    }
}

// copy one 18432-byte tile: 4 full chunks/thread + 1 for tid<128, fixed offsets
__device__ __forceinline__ void copy_tile(uint32_t sdst, const char* gsrc, int tid) {
    #pragma unroll
    for (int j = 0; j < 4; ++j)
        cp16(sdst + j * 4096, gsrc + j * 4096);
    if (tid < 128) cp16(sdst + 16384, gsrc + 16384);
}

// ================= fused attention =================
__global__ __launch_bounds__(256, 2)
void attn_fused(const float* __restrict__ Q, const int* __restrict__ pad,
                float* __restrict__ outO, float* __restrict__ outW)
{
    extern __shared__ __align__(16) char sm[];
    const int tid  = threadIdx.x;
    const int wid  = tid >> 5;
    const int lane = tid & 31;
    const int bh   = blockIdx.y;
    const int q0   = blockIdx.x * TQ;
    const int b    = bh / Hdim;
    const int sd   = q0 >> 7;      // diagonal slab index

    const uint32_t smb = smem_u32(sm);
    float* rowsum = (float*)(sm + RS_B);
    float* invp   = (float*)(sm + INV_B);
    float* pmf    = (float*)(sm + PM_B);   // [2][128] float pad

    const float* Qb = Q + ((size_t)bh * Sdim + q0) * Ddim;
    const int*   pb = pad + (size_t)b * Sdim;
    float* Wb = outW + ((size_t)bh * Sdim + q0) * Sdim;

    // per-thread fixed copy bases
    const char* gK = (const char*)g_kv + (size_t)bh * NSLAB * SLAB_B + tid * 16;
    const uint32_t kdst = smb + K_B + tid * 16;
    const uint32_t vdst = smb + V_B + tid * 16;

    // ---- prologue: stage Q*(0.125*log2e), issue K(0), V(0), pad[0] ----
    if (tid < TQ * Ddim / 4) {
        int q = tid >> 4, db = (tid & 15) * 4;
        float4 v = *(const float4*)(Qb + (size_t)q * Ddim + db);
        const float qs = 0.125f * 1.4426950408889634f;
        v.x *= qs; v.y *= qs; v.z *= qs; v.w *= qs;
        int base = q * TSTR + db * 2;
        split2h(sm + QS_HI_B, sm + QS_LO_B, base,     v.x, v.y);
        split2h(sm + QS_HI_B, sm + QS_LO_B, base + 4, v.z, v.w);
    }
    copy_tile(kdst, gK, tid);
    asm volatile("cp.async.commit_group;" ::: "memory");
    copy_tile(vdst, gK + TILE_B, tid);
    asm volatile("cp.async.commit_group;" ::: "memory");
    if (tid < NK) pmf[tid] = (float)pb[tid];
    if (tid < TQ) rowsum[tid] = 0.f;
    __syncthreads();

    // fragment address components
    const int arow  = lane & 15;
    const int apart = (lane >> 4) * 16;
    const int brow  = (lane & 7) + ((lane >> 4) << 3);
    const int bpart = ((lane >> 3) & 1) * 16;
    const int vrow  = (lane & 7) + (((lane >> 3) & 1) << 3);
    const int vpart = (lane >> 4) * 16;
    const int rlo   = lane >> 2;
    const int col0  = wid * 16 + (lane & 3) * 2;
    const int col1  = col0 + 8;
    float rs_lo = 0.f, rs_hi = 0.f;

    uint32_t aH[4][4], aL[4][4];
    #pragma unroll
    for (int ks = 0; ks < 4; ++ks) {
        ldsm4(smb + QS_HI_B + arow * TSTR + ks * 32 + apart,
              aH[ks][0], aH[ks][1], aH[ks][2], aH[ks][3]);
        ldsm4(smb + QS_LO_B + arow * TSTR + ks * 32 + apart,
              aL[ks][0], aL[ks][1], aL[ks][2], aL[ks][3]);
    }

    float co[8][4];
    #pragma unroll
    for (int t = 0; t < 8; ++t)
        #pragma unroll
        for (int j = 0; j < 4; ++j) co[t][j] = 0.f;

    const int qglo = q0 + rlo, qghi = qglo + 8;
    const uint32_t kbase = smb + K_B + (wid * 16 + brow) * TSTR + bpart;
    const uint32_t vbase = smb + V_B + (wid * 16 + vrow) * TSTR + vpart;
    // strip row pointers + running column offset
    char* srow0 = sm + STRIP_B + rlo * SSTR;
    char* srow1 = sm + STRIP_B + (rlo + 8) * SSTR;
    int soff = col0 * 2;   // advances 256 bytes per slab

    // ======================= mainloop =======================
    for (int s = 0; s < NSLAB; ++s) {
        const int buf = s & 1;

        // ---- K(s) ready ----
        asm volatile("cp.async.wait_group 1;" ::: "memory");
        __syncthreads();

        // ---- QK^T(s): 2 passes (Qhi+Qlo), warp's 16 k-cols ----
        float c[8];
        #pragma unroll
        for (int j = 0; j < 8; ++j) c[j] = 0.f;
        #pragma unroll
        for (int ks = 0; ks < 4; ++ks) {
            uint32_t b0, b1, b2, b3;
            ldsm4(kbase + ks * 32, b0, b1, b2, b3);
            mma16816(c,     aH[ks][0], aH[ks][1], aH[ks][2], aH[ks][3], b0, b1);
            mma16816(c + 4, aH[ks][0], aH[ks][1], aH[ks][2], aH[ks][3], b2, b3);
            mma16816(c,     aL[ks][0], aL[ks][1], aL[ks][2], aL[ks][3], b0, b1);
            mma16816(c + 4, aL[ks][0], aL[ks][1], aL[ks][2], aL[ks][3], b2, b3);
        }
        __syncthreads();   // all warps done reading K(s)

        // refresh K with K(s+1) + float pad
        if (s + 1 < NSLAB) {
            copy_tile(kdst, gK + SLAB_B, tid);
            if (tid < NK) pmf[(buf ^ 1) * 128 + tid] = (float)pb[(s + 1) * NK + tid];
        }
        asm volatile("cp.async.commit_group;" ::: "memory");

        // ---- epilogue(s): slab-class mask, exp2, rowsum, strip + A-frags ----
        uint32_t a0, a1, a2, a3;
        {
            const float* pmb = pmf + buf * 128;
            const float2 p0 = *(const float2*)&pmb[col0];
            const float2 p1 = *(const float2*)&pmb[col1];
            float x0 = exp2f(c[0]), x1 = exp2f(c[1]), x2 = exp2f(c[2]), x3 = exp2f(c[3]);
            float x4 = exp2f(c[4]), x5 = exp2f(c[5]), x6 = exp2f(c[6]), x7 = exp2f(c[7]);
            float e0, e1, e2, e3, e4, e5, e6, e7;
            if (s < sd) {          // past: masked iff pad==1
                e0 = x0 * (1.f - p0.x); e1 = x1 * (1.f - p0.y);
                e2 = x2 * (1.f - p0.x); e3 = x3 * (1.f - p0.y);
                e4 = x4 * (1.f - p1.x); e5 = x5 * (1.f - p1.y);
                e6 = x6 * (1.f - p1.x); e7 = x7 * (1.f - p1.y);
            } else if (s > sd) {   // future: masked iff pad==0 (1+1==2 stays unmasked)
                e0 = x0 * p0.x; e1 = x1 * p0.y;
                e2 = x2 * p0.x; e3 = x3 * p0.y;
                e4 = x4 * p1.x; e5 = x5 * p1.y;
                e6 = x6 * p1.x; e7 = x7 * p1.y;
            } else {               // diagonal slab: exact per-element test
                const int k0 = s << 7;
                const int kg0 = k0 + col0, kg1 = k0 + col1;
                e0 = ((((kg0     > qglo) ? 1.f : 0.f) + p0.x) == 1.f) ? 0.f : x0;
                e1 = ((((kg0 + 1 > qglo) ? 1.f : 0.f) + p0.y) == 1.f) ? 0.f : x1;
                e2 = ((((kg0     > qghi) ? 1.f : 0.f) + p0.x) == 1.f) ? 0.f : x2;
                e3 = ((((kg0 + 1 > qghi) ? 1.f : 0.f) + p0.y) == 1.f) ? 0.f : x3;
                e4 = ((((kg1     > qglo) ? 1.f : 0.f) + p1.x) == 1.f) ? 0.f : x4;
                e5 = ((((kg1 + 1 > qglo) ? 1.f : 0.f) + p1.y) == 1.f) ? 0.f : x5;
                e6 = ((((kg1     > qghi) ? 1.f : 0.f) + p1.x) == 1.f) ? 0.f : x6;
                e7 = ((((kg1 + 1 > qghi) ? 1.f : 0.f) + p1.y) == 1.f) ? 0.f : x7;
            }
            rs_lo += (e0 + e1) + (e4 + e5);
            rs_hi += (e2 + e3) + (e6 + e7);
            a0 = packh(e0, e1); a1 = packh(e2, e3);
            a2 = packh(e4, e5); a3 = packh(e6, e7);
            *(uint32_t*)(srow0 + soff)      = a0;
            *(uint32_t*)(srow1 + soff)      = a1;
            *(uint32_t*)(srow0 + soff + 16) = a2;
            *(uint32_t*)(srow1 + soff + 16) = a3;
        }
        soff += 256;

        // ---- V(s) ready ----
        asm volatile("cp.async.wait_group 1;" ::: "memory");
        __syncthreads();

        // ---- PV(s): warp-local k16, all 64 d-cols ----
        #pragma unroll
        for (int nt = 0; nt < 4; ++nt) {
            uint32_t v0, v1, v2, v3;
            ldsm4t(vbase + nt * 32, v0, v1, v2, v3);
            mma16816(co[2 * nt],     a0, a1, a2, a3, v0, v1);
            mma16816(co[2 * nt + 1], a0, a1, a2, a3, v2, v3);
        }
        __syncthreads();   // all warps done reading V(s)

        // refresh V with V(s+1)
        if (s + 1 < NSLAB)
            copy_tile(vdst, gK + SLAB_B + TILE_B, tid);
        asm volatile("cp.async.commit_group;" ::: "memory");
        gK += SLAB_B;
    }

    // ---- rowsums -> inv ----
    rs_lo += __shfl_xor_sync(0xffffffffu, rs_lo, 1);
    rs_lo += __shfl_xor_sync(0xffffffffu, rs_lo, 2);
    rs_hi += __shfl_xor_sync(0xffffffffu, rs_hi, 1);
    rs_hi += __shfl_xor_sync(0xffffffffu, rs_hi, 2);
    if ((lane & 3) == 0) {
        atomicAdd(&rowsum[rlo], rs_lo);
        atomicAdd(&rowsum[rlo + 8], rs_hi);
    }
    __syncthreads();
    if (tid < TQ) invp[tid] = 1.0f / rowsum[tid];

    // ---- store partial O to smem (reuse K/V region) ----
    {
        float* cosm = (float*)(sm + COSM_B) + wid * 16 * 68;
        const int dc = (lane & 3) * 2;
        #pragma unroll
        for (int t = 0; t < 8; ++t) {
            *(float2*)&cosm[rlo * 68 + t * 8 + dc]       = make_float2(co[t][0], co[t][1]);
            *(float2*)&cosm[(rlo + 8) * 68 + t * 8 + dc] = make_float2(co[t][2], co[t][3]);
        }
    }
    __syncthreads();

    // ---- W write (single pass, normalized, coalesced from strip) ----
    for (int i = tid; i < TQ * (Sdim / 4); i += 256) {
        int q = i >> 9, c4 = (i & 511) * 4;
        const uint32_t* sp = (const uint32_t*)(sm + STRIP_B + q * SSTR + c4 * 2);
        uint32_t u0 = sp[0], u1 = sp[1];
        float2 lo = __half22float2(*(__half2*)&u0);
        float2 hi = __half22float2(*(__half2*)&u1);
        const float iv = invp[q];
        float4 w = make_float4(lo.x * iv, lo.y * iv, hi.x * iv, hi.y * iv);
        __stcs((float4*)&Wb[(size_t)q * Sdim + c4], w);
    }

    // ---- O reduce across 8 warps + store ----
    {
        const int q = tid >> 4;
        const int d = (tid & 15) * 4;
        const float* cosm = (const float*)(sm + COSM_B);
        float4 acc = make_float4(0.f, 0.f, 0.f, 0.f);
        #pragma unroll
        for (int w = 0; w < 8; ++w) {
            float4 t = *(const float4*)&cosm[(w * 16 + q) * 68 + d];
            acc.x += t.x; acc.y += t.y; acc.z += t.z; acc.w += t.w;
        }
        const float iv = invp[q];
        acc.x *= iv; acc.y *= iv; acc.z *= iv; acc.w *= iv;
        *(float4*)&outO[((size_t)bh * Sdim + q0 + q) * Ddim + d] = acc;
    }
}

extern "C" void kernel_launch(void* const* d_in, const int* in_sizes, int n_in,
                              void* d_out, int out_size)
{
    const float* Q   = (const float*)d_in[0];
    const float* K   = (const float*)d_in[1];
    const float* V   = (const float*)d_in[2];
    const int*   pad = (const int*)d_in[3];

    const long long nres = (long long)BHdim * Sdim * Ddim;
    float* outO = (float*)d_out;
    float* outW = outO + nres;   // out = (result, attention_weights)

    dim3 pgrid(NSLAB, BHdim);
    prep_kv<<<pgrid, 256>>>(K, V);

    cudaFuncSetAttribute(attn_fused, cudaFuncAttributeMaxDynamicSharedMemorySize, SMEM_TOTAL);
    dim3 grid(Sdim / TQ, BHdim);
    attn_fused<<<grid, 256, SMEM_TOTAL>>>(Q, pad, outO, outW);
}

// round 17
// speedup vs baseline: 2.1807x; 1.0667x over previous
#include <cuda_runtime.h>
#include <cuda_fp16.h>
#include <stdint.h>
#include <math.h>

// ---------------- problem constants ----------------
constexpr int Sdim = 2048, Hdim = 16, BHdim = 64, Ddim = 64;
constexpr int TQ = 16;            // query rows per CTA (one MMA M-tile)
constexpr int NK = 128;           // key slab (8 warps x 16 k-cols)
constexpr int NSLAB = Sdim / NK;  // 16

constexpr int TSTR = 144;         // bytes per fp16 K/V/Q tile row (64+8 elems)
constexpr int TILE_B = NK * TSTR;            // 18432 (one K or V tile)
constexpr int SLAB_B = 2 * TILE_B;           // K | V = 36864
__device__ __align__(16) unsigned char g_kv[(size_t)BHdim * NSLAB * SLAB_B];

// ---------------- smem layout (byte offsets) ----------------
constexpr int SSTR    = 4112;     // strip row stride bytes (2048+8 halfs)
constexpr int RS_B    = 0;        // f32[16]
constexpr int INV_B   = 64;       // f32[16]
constexpr int PM_B    = 128;      // f32[2][128] pad mask as float
constexpr int QS_B    = 1152;     // [16][72] fp16 = 2304 (single precision level)
constexpr int K_B     = 5760;     // K tile 18432 (single buffer, in-place refresh)
constexpr int V_B     = 24192;    // V tile 18432
constexpr int STRIP_B = 42624;    // fp16 [16][2056] = 65792
constexpr int SMEM_TOTAL = 108416;   // x2 CTAs fits 228KB SM
constexpr int COSM_B  = K_B;      // reused after mainloop: f32 [8][16][68]

// ---------------- helpers ----------------
__device__ __forceinline__ uint32_t smem_u32(const void* p) {
    uint32_t a;
    asm("{ .reg .u64 t; cvta.to.shared.u64 t, %1; cvt.u32.u64 %0, t; }" : "=r"(a) : "l"(p));
    return a;
}
__device__ __forceinline__ void cp16(uint32_t sdst, const void* gsrc) {
    asm volatile("cp.async.cg.shared.global [%0], [%1], 16;" :: "r"(sdst), "l"(gsrc));
}
__device__ __forceinline__ void ldsm4(uint32_t addr, uint32_t& r0, uint32_t& r1,
                                      uint32_t& r2, uint32_t& r3) {
    asm volatile("ldmatrix.sync.aligned.m8n8.x4.shared.b16 {%0,%1,%2,%3}, [%4];"
                 : "=r"(r0), "=r"(r1), "=r"(r2), "=r"(r3) : "r"(addr));
}
__device__ __forceinline__ void ldsm4t(uint32_t addr, uint32_t& r0, uint32_t& r1,
                                       uint32_t& r2, uint32_t& r3) {
    asm volatile("ldmatrix.sync.aligned.m8n8.x4.trans.shared.b16 {%0,%1,%2,%3}, [%4];"
                 : "=r"(r0), "=r"(r1), "=r"(r2), "=r"(r3) : "r"(addr));
}
__device__ __forceinline__ void mma16816(float* c, uint32_t a0, uint32_t a1,
                                         uint32_t a2, uint32_t a3,
                                         uint32_t b0, uint32_t b1) {
    asm volatile(
        "mma.sync.aligned.m16n8k16.row.col.f32.f16.f16.f32 "
        "{%0,%1,%2,%3}, {%4,%5,%6,%7}, {%8,%9}, {%0,%1,%2,%3};"
        : "+f"(c[0]), "+f"(c[1]), "+f"(c[2]), "+f"(c[3])
        : "r"(a0), "r"(a1), "r"(a2), "r"(a3), "r"(b0), "r"(b1));
}
__device__ __forceinline__ void cvt2h(char* dst, int off, float a, float b) {
    *(__half2*)(dst + off) = __halves2half2(__float2half_rn(a), __float2half_rn(b));
}
__device__ __forceinline__ uint32_t packh(float a, float b) {
    __half2 h = __halves2half2(__float2half_rn(a), __float2half_rn(b));
    return *(uint32_t*)&h;
}

// ================= preprocessing: K,V fp32 -> tiled fp16 =================
__global__ __launch_bounds__(256)
void prep_kv(const float* __restrict__ K, const float* __restrict__ V)
{
    const int s  = blockIdx.x;
    const int bh = blockIdx.y;
    const int tid = threadIdx.x;
    const float* Kb = K + ((size_t)bh * Sdim + s * NK) * Ddim;
    const float* Vb = V + ((size_t)bh * Sdim + s * NK) * Ddim;
    char* dst = (char*)g_kv + ((size_t)bh * NSLAB + s) * SLAB_B;

    for (int i = tid; i < NK * Ddim / 4; i += 256) {
        int k = i >> 4, db = (i & 15) * 4;
        int off = k * TSTR + db * 2;
        float4 kv4 = *(const float4*)(Kb + (size_t)k * Ddim + db);
        cvt2h(dst, off,     kv4.x, kv4.y);
        cvt2h(dst, off + 4, kv4.z, kv4.w);
        float4 vv4 = *(const float4*)(Vb + (size_t)k * Ddim + db);
        cvt2h(dst + TILE_B, off,     vv4.x, vv4.y);
        cvt2h(dst + TILE_B, off + 4, vv4.z, vv4.w);
    }
}

// copy one 18432-byte tile: 4 full chunks/thread + 1 for tid<128, fixed offsets
__device__ __forceinline__ void copy_tile(uint32_t sdst, const char* gsrc, int tid) {
    #pragma unroll
    for (int j = 0; j < 4; ++j)
        cp16(sdst + j * 4096, gsrc + j * 4096);
    if (tid < 128) cp16(sdst + 16384, gsrc + 16384);
}

// ================= fused attention =================
__global__ __launch_bounds__(256, 2)
void attn_fused(const float* __restrict__ Q, const int* __restrict__ pad,
                float* __restrict__ outO, float* __restrict__ outW)
{
    extern __shared__ __align__(16) char sm[];
    const int tid  = threadIdx.x;
    const int wid  = tid >> 5;
    const int lane = tid & 31;
    const int bh   = blockIdx.y;
    const int q0   = blockIdx.x * TQ;
    const int b    = bh / Hdim;
    const int sd   = q0 >> 7;      // diagonal slab index

    const uint32_t smb = smem_u32(sm);
    float* rowsum = (float*)(sm + RS_B);
    float* invp   = (float*)(sm + INV_B);
    float* pmf    = (float*)(sm + PM_B);   // [2][128] float pad

    const float* Qb = Q + ((size_t)bh * Sdim + q0) * Ddim;
    const int*   pb = pad + (size_t)b * Sdim;
    float* Wb = outW + ((size_t)bh * Sdim + q0) * Sdim;

    // per-thread fixed copy bases
    const char* gK = (const char*)g_kv + (size_t)bh * NSLAB * SLAB_B + tid * 16;
    const uint32_t kdst = smb + K_B + tid * 16;
    const uint32_t vdst = smb + V_B + tid * 16;

    // ---- prologue: stage Q*(0.125*log2e) fp16, issue K(0), V(0), pad[0] ----
    if (tid < TQ * Ddim / 4) {
        int q = tid >> 4, db = (tid & 15) * 4;
        float4 v = *(const float4*)(Qb + (size_t)q * Ddim + db);
        const float qs = 0.125f * 1.4426950408889634f;
        v.x *= qs; v.y *= qs; v.z *= qs; v.w *= qs;
        int base = q * TSTR + db * 2;
        cvt2h(sm + QS_B, base,     v.x, v.y);
        cvt2h(sm + QS_B, base + 4, v.z, v.w);
    }
    copy_tile(kdst, gK, tid);
    asm volatile("cp.async.commit_group;" ::: "memory");
    copy_tile(vdst, gK + TILE_B, tid);
    asm volatile("cp.async.commit_group;" ::: "memory");
    if (tid < NK) pmf[tid] = (float)pb[tid];
    if (tid < TQ) rowsum[tid] = 0.f;
    __syncthreads();

    // fragment address components
    const int arow  = lane & 15;
    const int apart = (lane >> 4) * 16;
    const int brow  = (lane & 7) + ((lane >> 4) << 3);
    const int bpart = ((lane >> 3) & 1) * 16;
    const int vrow  = (lane & 7) + (((lane >> 3) & 1) << 3);
    const int vpart = (lane >> 4) * 16;
    const int rlo   = lane >> 2;
    const int col0  = wid * 16 + (lane & 3) * 2;
    const int col1  = col0 + 8;
    float rs_lo = 0.f, rs_hi = 0.f;

    // hoist Q A-fragments (single precision level)
    uint32_t aQ[4][4];
    #pragma unroll
    for (int ks = 0; ks < 4; ++ks)
        ldsm4(smb + QS_B + arow * TSTR + ks * 32 + apart,
              aQ[ks][0], aQ[ks][1], aQ[ks][2], aQ[ks][3]);

    float co[8][4];
    #pragma unroll
    for (int t = 0; t < 8; ++t)
        #pragma unroll
        for (int j = 0; j < 4; ++j) co[t][j] = 0.f;

    const int qglo = q0 + rlo, qghi = qglo + 8;
    const uint32_t kbase = smb + K_B + (wid * 16 + brow) * TSTR + bpart;
    const uint32_t vbase = smb + V_B + (wid * 16 + vrow) * TSTR + vpart;
    char* srow0 = sm + STRIP_B + rlo * SSTR;
    char* srow1 = sm + STRIP_B + (rlo + 8) * SSTR;
    int soff = col0 * 2;   // advances 256 bytes per slab

    // ======================= mainloop =======================
    for (int s = 0; s < NSLAB; ++s) {
        const int buf = s & 1;

        // ---- K(s) ready ----
        asm volatile("cp.async.wait_group 1;" ::: "memory");
        __syncthreads();

        // ---- QK^T(s): single fp16 pass, warp's 16 k-cols ----
        float c[8];
        #pragma unroll
        for (int j = 0; j < 8; ++j) c[j] = 0.f;
        #pragma unroll
        for (int ks = 0; ks < 4; ++ks) {
            uint32_t b0, b1, b2, b3;
            ldsm4(kbase + ks * 32, b0, b1, b2, b3);
            mma16816(c,     aQ[ks][0], aQ[ks][1], aQ[ks][2], aQ[ks][3], b0, b1);
            mma16816(c + 4, aQ[ks][0], aQ[ks][1], aQ[ks][2], aQ[ks][3], b2, b3);
        }
        __syncthreads();   // all warps done reading K(s)

        // refresh K with K(s+1) + float pad
        if (s + 1 < NSLAB) {
            copy_tile(kdst, gK + SLAB_B, tid);
            if (tid < NK) pmf[(buf ^ 1) * 128 + tid] = (float)pb[(s + 1) * NK + tid];
        }
        asm volatile("cp.async.commit_group;" ::: "memory");

        // ---- epilogue(s): slab-class mask, exp2, rowsum, strip + A-frags ----
        uint32_t a0, a1, a2, a3;
        {
            const float* pmb = pmf + buf * 128;
            const float2 p0 = *(const float2*)&pmb[col0];
            const float2 p1 = *(const float2*)&pmb[col1];
            float x0 = exp2f(c[0]), x1 = exp2f(c[1]), x2 = exp2f(c[2]), x3 = exp2f(c[3]);
            float x4 = exp2f(c[4]), x5 = exp2f(c[5]), x6 = exp2f(c[6]), x7 = exp2f(c[7]);
            float e0, e1, e2, e3, e4, e5, e6, e7;
            if (s < sd) {          // past: masked iff pad==1
                e0 = x0 * (1.f - p0.x); e1 = x1 * (1.f - p0.y);
                e2 = x2 * (1.f - p0.x); e3 = x3 * (1.f - p0.y);
                e4 = x4 * (1.f - p1.x); e5 = x5 * (1.f - p1.y);
                e6 = x6 * (1.f - p1.x); e7 = x7 * (1.f - p1.y);
            } else if (s > sd) {   // future: masked iff pad==0 (1+1==2 stays unmasked)
                e0 = x0 * p0.x; e1 = x1 * p0.y;
                e2 = x2 * p0.x; e3 = x3 * p0.y;
                e4 = x4 * p1.x; e5 = x5 * p1.y;
                e6 = x6 * p1.x; e7 = x7 * p1.y;
            } else {               // diagonal slab: exact per-element test
                const int k0 = s << 7;
                const int kg0 = k0 + col0, kg1 = k0 + col1;
                e0 = ((((kg0     > qglo) ? 1.f : 0.f) + p0.x) == 1.f) ? 0.f : x0;
                e1 = ((((kg0 + 1 > qglo) ? 1.f : 0.f) + p0.y) == 1.f) ? 0.f : x1;
                e2 = ((((kg0     > qghi) ? 1.f : 0.f) + p0.x) == 1.f) ? 0.f : x2;
                e3 = ((((kg0 + 1 > qghi) ? 1.f : 0.f) + p0.y) == 1.f) ? 0.f : x3;
                e4 = ((((kg1     > qglo) ? 1.f : 0.f) + p1.x) == 1.f) ? 0.f : x4;
                e5 = ((((kg1 + 1 > qglo) ? 1.f : 0.f) + p1.y) == 1.f) ? 0.f : x5;
                e6 = ((((kg1     > qghi) ? 1.f : 0.f) + p1.x) == 1.f) ? 0.f : x6;
                e7 = ((((kg1 + 1 > qghi) ? 1.f : 0.f) + p1.y) == 1.f) ? 0.f : x7;
            }
            rs_lo += (e0 + e1) + (e4 + e5);
            rs_hi += (e2 + e3) + (e6 + e7);
            a0 = packh(e0, e1); a1 = packh(e2, e3);
            a2 = packh(e4, e5); a3 = packh(e6, e7);
            *(uint32_t*)(srow0 + soff)      = a0;
            *(uint32_t*)(srow1 + soff)      = a1;
            *(uint32_t*)(srow0 + soff + 16) = a2;
            *(uint32_t*)(srow1 + soff + 16) = a3;
        }
        soff += 256;

        // ---- V(s) ready ----
        asm volatile("cp.async.wait_group 1;" ::: "memory");
        __syncthreads();

        // ---- PV(s): warp-local k16, all 64 d-cols ----
        #pragma unroll
        for (int nt = 0; nt < 4; ++nt) {
            uint32_t v0, v1, v2, v3;
            ldsm4t(vbase + nt * 32, v0, v1, v2, v3);
            mma16816(co[2 * nt],     a0, a1, a2, a3, v0, v1);
            mma16816(co[2 * nt + 1], a0, a1, a2, a3, v2, v3);
        }
        __syncthreads();   // all warps done reading V(s)

        // refresh V with V(s+1)
        if (s + 1 < NSLAB)
            copy_tile(vdst, gK + SLAB_B + TILE_B, tid);
        asm volatile("cp.async.commit_group;" ::: "memory");
        gK += SLAB_B;
    }

    // ---- rowsums -> inv ----
    rs_lo += __shfl_xor_sync(0xffffffffu, rs_lo, 1);
    rs_lo += __shfl_xor_sync(0xffffffffu, rs_lo, 2);
    rs_hi += __shfl_xor_sync(0xffffffffu, rs_hi, 1);
    rs_hi += __shfl_xor_sync(0xffffffffu, rs_hi, 2);
    if ((lane & 3) == 0) {
        atomicAdd(&rowsum[rlo], rs_lo);
        atomicAdd(&rowsum[rlo + 8], rs_hi);
    }
    __syncthreads();
    if (tid < TQ) invp[tid] = 1.0f / rowsum[tid];

    // ---- store partial O to smem (reuse K/V region) ----
    {
        float* cosm = (float*)(sm + COSM_B) + wid * 16 * 68;
        const int dc = (lane & 3) * 2;
        #pragma unroll
        for (int t = 0; t < 8; ++t) {
            *(float2*)&cosm[rlo * 68 + t * 8 + dc]       = make_float2(co[t][0], co[t][1]);
            *(float2*)&cosm[(rlo + 8) * 68 + t * 8 + dc] = make_float2(co[t][2], co[t][3]);
        }
    }
    __syncthreads();

    // ---- W write (single pass, normalized, coalesced from strip) ----
    for (int i = tid; i < TQ * (Sdim / 4); i += 256) {
        int q = i >> 9, c4 = (i & 511) * 4;
        const uint32_t* sp = (const uint32_t*)(sm + STRIP_B + q * SSTR + c4 * 2);
        uint32_t u0 = sp[0], u1 = sp[1];
        float2 lo = __half22float2(*(__half2*)&u0);
        float2 hi = __half22float2(*(__half2*)&u1);
        const float iv = invp[q];
        float4 w = make_float4(lo.x * iv, lo.y * iv, hi.x * iv, hi.y * iv);
        __stcs((float4*)&Wb[(size_t)q * Sdim + c4], w);
    }

    // ---- O reduce across 8 warps + store ----
    {
        const int q = tid >> 4;
        const int d = (tid & 15) * 4;
        const float* cosm = (const float*)(sm + COSM_B);
        float4 acc = make_float4(0.f, 0.f, 0.f, 0.f);
        #pragma unroll
        for (int w = 0; w < 8; ++w) {
            float4 t = *(const float4*)&cosm[(w * 16 + q) * 68 + d];
            acc.x += t.x; acc.y += t.y; acc.z += t.z; acc.w += t.w;
        }
        const float iv = invp[q];
        acc.x *= iv; acc.y *= iv; acc.z *= iv; acc.w *= iv;
        *(float4*)&outO[((size_t)bh * Sdim + q0 + q) * Ddim + d] = acc;
    }
}

extern "C" void kernel_launch(void* const* d_in, const int* in_sizes, int n_in,
                              void* d_out, int out_size)
{
    const float* Q   = (const float*)d_in[0];
    const float* K   = (const float*)d_in[1];
    const float* V   = (const float*)d_in[2];
    const int*   pad = (const int*)d_in[3];

    const long long nres = (long long)BHdim * Sdim * Ddim;
    float* outO = (float*)d_out;
    float* outW = outO + nres;   // out = (result, attention_weights)

    dim3 pgrid(NSLAB, BHdim);
    prep_kv<<<pgrid, 256>>>(K, V);

    cudaFuncSetAttribute(attn_fused, cudaFuncAttributeMaxDynamicSharedMemorySize, SMEM_TOTAL);
    dim3 grid(Sdim / TQ, BHdim);
    attn_fused<<<grid, 256, SMEM_TOTAL>>>(Q, pad, outO, outW);
}